// round 7
// baseline (speedup 1.0000x reference)
#include <cuda_runtime.h>
#include <cuda_fp16.h>
#include <math.h>
#include <stdint.h>

#define N_NODES 50000
#define N_PAD   50176          // 392 * 128
#define N_EDGES 600000
#define IN_DIM  128
#define HID_DIM 512

// ---------------- scratch ----------------------------------------------------
__device__ int   g_cnt[N_NODES];          // zero-init at load; final_kernel re-zeroes
__device__ int   g_row[N_NODES + 1];
__device__ int   g_cursor[N_NODES];
__device__ int   g_csr[N_EDGES];
__device__ float g_invd[N_NODES];
__device__ __align__(16) __half g_xh  [N_PAD * IN_DIM];
__device__ __align__(16) __half g_aggh[N_PAD * IN_DIM];
__device__ __align__(16) __half g_Wh  [256 * HID_DIM];    // [k][n]: k<128 W1l else W1r
__device__ float g_pq[N_NODES * 4];

__device__ __forceinline__ uint32_t packh2(float a, float b) {
    __half2 h = __floats2half2_rn(a, b);
    return *reinterpret_cast<uint32_t*>(&h);
}

// ---------------- 0. prep: zero pq + convert x/W + histogram -------------------
__global__ void prep_kernel(const float* __restrict__ x,
                            const float* __restrict__ W1l,
                            const float* __restrict__ W1r,
                            const int* __restrict__ edge_index) {
    int i = blockIdx.x * blockDim.x + threadIdx.x;
    if (i < N_NODES * 4) g_pq[i] = 0.f;
    if (i < N_EDGES) atomicAdd(&g_cnt[edge_index[N_EDGES + i]], 1);
    const int xtot = N_PAD * IN_DIM / 8;
    if (i < xtot) {
        long long base = (long long)i * 8;
        int m = (int)(base / IN_DIM);
        uint4 o;
        if (m < N_NODES) {
            float4 v0 = *reinterpret_cast<const float4*>(x + base);
            float4 v1 = *reinterpret_cast<const float4*>(x + base + 4);
            o.x = packh2(v0.x, v0.y); o.y = packh2(v0.z, v0.w);
            o.z = packh2(v1.x, v1.y); o.w = packh2(v1.z, v1.w);
        } else o = make_uint4(0, 0, 0, 0);
        *reinterpret_cast<uint4*>(g_xh + base) = o;
    }
    const int wtot = 256 * HID_DIM / 4;
    if (i < wtot) {
        int base = i * 4;
        int k = base >> 9;
        int n = base & 511;
        const float* W = (k < IN_DIM) ? (W1l + k * HID_DIM + n)
                                      : (W1r + (k - IN_DIM) * HID_DIM + n);
        float4 v = *reinterpret_cast<const float4*>(W);
        uint2 o; o.x = packh2(v.x, v.y); o.y = packh2(v.z, v.w);
        *reinterpret_cast<uint2*>(g_Wh + base) = o;
    }
}

// ---------------- 1. scan -------------------------------------------------------
__global__ void scan_kernel() {
    __shared__ int partial[1024];
    const int t = threadIdx.x;
    const int CHUNK = (N_NODES + 1023) / 1024;
    const int beg = t * CHUNK;
    const int end = min(beg + CHUNK, N_NODES);
    int sum = 0;
    for (int i = beg; i < end; i++) sum += g_cnt[i];
    partial[t] = sum;
    __syncthreads();
    for (int off = 1; off < 1024; off <<= 1) {
        int u = (t >= off) ? partial[t - off] : 0;
        __syncthreads();
        partial[t] += u;
        __syncthreads();
    }
    int run = partial[t] - sum;
    for (int i = beg; i < end; i++) {
        int c = g_cnt[i];
        g_row[i] = run;
        g_cursor[i] = run;
        g_invd[i] = 1.f / fmaxf((float)c, 1.f);
        run += c;
    }
    if (t == 0) g_row[N_NODES] = N_EDGES;
}

// ---------------- 2. reorder ----------------------------------------------------
__global__ void reorder_kernel(const int* __restrict__ edge_index) {
    int e = blockIdx.x * blockDim.x + threadIdx.x;
    if (e >= N_EDGES) return;
    int src = edge_index[e];
    int dst = edge_index[N_EDGES + e];
    int pos = atomicAdd(&g_cursor[dst], 1);
    g_csr[pos] = src;
}

// ---------------- 3. gather-mean aggregation (f16 reads, 16 lanes/node) ----------
__global__ void aggregate1_kernel() {
    int id = blockIdx.x * blockDim.x + threadIdx.x;
    int node = id >> 4;
    int l16 = id & 15;
    if (node >= N_PAD) return;
    float s[8] = {};
    if (node < N_NODES) {
        const int beg = g_row[node];
        const int end = g_row[node + 1];
        int e = beg;
        for (; e + 1 < end; e += 2) {
            int s0 = g_csr[e], s1 = g_csr[e + 1];
            uint4 v0 = *reinterpret_cast<const uint4*>(g_xh + (long long)s0 * IN_DIM + l16 * 8);
            uint4 v1 = *reinterpret_cast<const uint4*>(g_xh + (long long)s1 * IN_DIM + l16 * 8);
            const __half2* h0 = reinterpret_cast<const __half2*>(&v0);
            const __half2* h1 = reinterpret_cast<const __half2*>(&v1);
            #pragma unroll
            for (int j = 0; j < 4; j++) {
                float2 f0 = __half22float2(h0[j]);
                float2 f1 = __half22float2(h1[j]);
                s[j * 2 + 0] += f0.x + f1.x;
                s[j * 2 + 1] += f0.y + f1.y;
            }
        }
        if (e < end) {
            int s0 = g_csr[e];
            uint4 v0 = *reinterpret_cast<const uint4*>(g_xh + (long long)s0 * IN_DIM + l16 * 8);
            const __half2* h0 = reinterpret_cast<const __half2*>(&v0);
            #pragma unroll
            for (int j = 0; j < 4; j++) {
                float2 f0 = __half22float2(h0[j]);
                s[j * 2 + 0] += f0.x;
                s[j * 2 + 1] += f0.y;
            }
        }
        const float invd = g_invd[node];
        #pragma unroll
        for (int j = 0; j < 8; j++) s[j] *= invd;
    }
    uint4 o;
    o.x = packh2(s[0], s[1]); o.y = packh2(s[2], s[3]);
    o.z = packh2(s[4], s[5]); o.w = packh2(s[6], s[7]);
    *reinterpret_cast<uint4*>(g_aggh + (long long)node * IN_DIM + l16 * 8) = o;
}

// ---------------- mma helpers ----------------------------------------------------
__device__ __forceinline__ void ldsm_x4(uint32_t* r, uint32_t addr) {
    asm volatile("ldmatrix.sync.aligned.m8n8.x4.shared.b16 {%0,%1,%2,%3}, [%4];"
                 : "=r"(r[0]), "=r"(r[1]), "=r"(r[2]), "=r"(r[3]) : "r"(addr));
}
__device__ __forceinline__ void ldsm_x2t(uint32_t* r, uint32_t addr) {
    asm volatile("ldmatrix.sync.aligned.m8n8.x2.trans.shared.b16 {%0,%1}, [%2];"
                 : "=r"(r[0]), "=r"(r[1]) : "r"(addr));
}
__device__ __forceinline__ void mma_f16(float* d, const uint32_t* a, const uint32_t* b) {
    asm volatile(
        "mma.sync.aligned.m16n8k16.row.col.f32.f16.f16.f32 "
        "{%0,%1,%2,%3}, {%4,%5,%6,%7}, {%8,%9}, {%0,%1,%2,%3};"
        : "+f"(d[0]), "+f"(d[1]), "+f"(d[2]), "+f"(d[3])
        : "r"(a[0]), "r"(a[1]), "r"(a[2]), "r"(a[3]), "r"(b[0]), "r"(b[1]));
}
__device__ __forceinline__ void cp16(uint32_t smem_addr, const void* gptr) {
    asm volatile("cp.async.cg.shared.global [%0], [%1], 16;"
                 :: "r"(smem_addr), "l"(gptr) : "memory");
}

// ---------------- 4. layer-1 GEMM: full-K resident, one sync ---------------------
// BM=128, BN=128, K=256 fully in smem. 256 threads, warp grid 2x4, warp tile 64x32.
#define SA 264      // A row stride in halfs (256+8): 528B, 16B aligned
#define SB 136      // B row stride in halfs (128+8): 272B
#define SM_AS 0
#define SM_BS (128 * SA * 2)                 // 67584
#define SM_WC (SM_BS + 256 * SB * 2)         // 67584+69632 = 137216
#define SM_BIAS (SM_WC + 128 * 4 * 4)        // +2048 = 139264
#define SM_TOTAL (SM_BIAS + 128 * 4)         // +512 = 139776

__global__ __launch_bounds__(256, 1)
void gemm1_kernel(const float* __restrict__ b1,
                  const float* __restrict__ W2l,
                  const float* __restrict__ W2r) {
    extern __shared__ __align__(16) char smem[];
    __half* As = reinterpret_cast<__half*>(smem + SM_AS);
    __half* Bs = reinterpret_cast<__half*>(smem + SM_BS);
    float (*Wc)[4] = reinterpret_cast<float(*)[4]>(smem + SM_WC);
    float* bias_s = reinterpret_cast<float*>(smem + SM_BIAS);

    const int block_m = blockIdx.y * 128;
    const int block_n = blockIdx.x * 128;
    const int tid  = threadIdx.x;
    const int warp = tid >> 5;
    const int lane = tid & 31;
    const int wm = warp >> 2;
    const int wn = warp & 3;
    const int g  = lane >> 2;
    const int t  = lane & 3;

    const uint32_t sm_base = (uint32_t)__cvta_generic_to_shared(smem);
    const uint32_t as_u = sm_base + SM_AS;
    const uint32_t bs_u = sm_base + SM_BS;

    // ---- async-load the full A slab (128x256) and B slab (256x128) ----
    #pragma unroll
    for (int i = 0; i < 16; i++) {
        int id = tid + i * 256;            // 0..4095
        int row = id >> 5;                 // 0..127
        int kh = (id & 31) * 8;            // 0..248
        const __half* src = (kh < IN_DIM)
            ? (g_aggh + (long long)(block_m + row) * IN_DIM + kh)
            : (g_xh + (long long)(block_m + row) * IN_DIM + (kh - IN_DIM));
        cp16(as_u + (row * SA + kh) * 2, src);
    }
    #pragma unroll
    for (int i = 0; i < 16; i++) {
        int id = tid + i * 256;            // 0..4095
        int k = id >> 4;                   // 0..255
        int nc = (id & 15) * 8;            // 0..120
        cp16(bs_u + (k * SB + nc) * 2, g_Wh + k * HID_DIM + block_n + nc);
    }
    asm volatile("cp.async.commit_group;" ::: "memory");

    // epilogue weights/bias (regular smem stores, overlap with cp.async)
    for (int idx = tid; idx < 128 * 4; idx += 256) {
        int nn = idx >> 2, c = idx & 3;
        int n = block_n + nn;
        Wc[nn][c] = (c < 2) ? W2l[n * 2 + c] : W2r[n * 2 + (c - 2)];
    }
    for (int idx = tid; idx < 128; idx += 256) bias_s[idx] = b1[block_n + idx];

    asm volatile("cp.async.wait_group 0;" ::: "memory");
    __syncthreads();

    // ---- 16 k16 steps, no further syncs ----
    const uint32_t a_lane = as_u + ((wm * 64 + (lane & 15)) * SA + (lane >> 4) * 8) * 2;
    const uint32_t b_lane = bs_u + ((lane & 15) * SB + wn * 32) * 2;

    float acc[4][4][4] = {};
    #pragma unroll 4
    for (int ks = 0; ks < 16; ks++) {
        const int kk = ks * 16;
        uint32_t af[4][4], bf[4][2];
        #pragma unroll
        for (int mi = 0; mi < 4; mi++)
            ldsm_x4(af[mi], a_lane + (mi * 16 * SA + kk) * 2);
        #pragma unroll
        for (int ni = 0; ni < 4; ni++)
            ldsm_x2t(bf[ni], b_lane + (kk * SB + ni * 8) * 2);
        #pragma unroll
        for (int mi = 0; mi < 4; mi++)
            #pragma unroll
            for (int ni = 0; ni < 4; ni++)
                mma_f16(acc[mi][ni], af[mi], bf[ni]);
    }

    // ---- epilogue: bias + relu, project to 4 outputs, reduce over t-quad ----
    #pragma unroll
    for (int mi = 0; mi < 4; mi++) {
        #pragma unroll
        for (int half = 0; half < 2; half++) {
            const int m = block_m + wm * 64 + mi * 16 + g + half * 8;
            float s0 = 0.f, s1 = 0.f, s2 = 0.f, s3 = 0.f;
            #pragma unroll
            for (int ni = 0; ni < 4; ni++) {
                #pragma unroll
                for (int r = 0; r < 2; r++) {
                    const int nl = wn * 32 + ni * 8 + 2 * t + r;
                    float hv = fmaxf(acc[mi][ni][half * 2 + r] + bias_s[nl], 0.f);
                    s0 += hv * Wc[nl][0];
                    s1 += hv * Wc[nl][1];
                    s2 += hv * Wc[nl][2];
                    s3 += hv * Wc[nl][3];
                }
            }
            #pragma unroll
            for (int off = 1; off <= 2; off <<= 1) {
                s0 += __shfl_xor_sync(0xffffffff, s0, off);
                s1 += __shfl_xor_sync(0xffffffff, s1, off);
                s2 += __shfl_xor_sync(0xffffffff, s2, off);
                s3 += __shfl_xor_sync(0xffffffff, s3, off);
            }
            if (t == 0 && m < N_NODES) {
                atomicAdd(&g_pq[m * 4 + 0], s0);
                atomicAdd(&g_pq[m * 4 + 1], s1);
                atomicAdd(&g_pq[m * 4 + 2], s2);
                atomicAdd(&g_pq[m * 4 + 3], s3);
            }
        }
    }
}

// ---------------- 5. final: gather + log_softmax + reset g_cnt -------------------
__global__ void final_kernel(const float* __restrict__ b2,
                             float* __restrict__ out) {
    int n = blockIdx.x * blockDim.x + threadIdx.x;
    if (n >= N_NODES) return;
    g_cnt[n] = 0;   // restore invariant for next invocation / graph replay
    const int beg = g_row[n];
    const int end = g_row[n + 1];
    float s0 = 0.f, s1 = 0.f;
    int e = beg;
    for (; e + 1 < end; e += 2) {
        int u = g_csr[e], v = g_csr[e + 1];
        float2 pu = *reinterpret_cast<const float2*>(&g_pq[u * 4]);
        float2 pv = *reinterpret_cast<const float2*>(&g_pq[v * 4]);
        s0 += pu.x + pv.x; s1 += pu.y + pv.y;
    }
    if (e < end) {
        int u = g_csr[e];
        float2 pu = *reinterpret_cast<const float2*>(&g_pq[u * 4]);
        s0 += pu.x; s1 += pu.y;
    }
    const float invd = g_invd[n];
    float o0 = s0 * invd + b2[0] + g_pq[n * 4 + 2];
    float o1 = s1 * invd + b2[1] + g_pq[n * 4 + 3];
    float m = fmaxf(o0, o1);
    float lse = m + logf(expf(o0 - m) + expf(o1 - m));
    out[n * 2 + 0] = o0 - lse;
    out[n * 2 + 1] = o1 - lse;
}

// ---------------- launcher ---------------------------------------------------------
extern "C" void kernel_launch(void* const* d_in, const int* in_sizes, int n_in,
                              void* d_out, int out_size) {
    const float* x    = (const float*)d_in[0];
    const float* W1l  = (const float*)d_in[1];
    const float* b1   = (const float*)d_in[2];
    const float* W1r  = (const float*)d_in[3];
    const float* W2l  = (const float*)d_in[4];
    const float* b2   = (const float*)d_in[5];
    const float* W2r  = (const float*)d_in[6];
    const int*   ei   = (const int*)d_in[7];
    float* out = (float*)d_out;

    cudaFuncSetAttribute(gemm1_kernel,
                         cudaFuncAttributeMaxDynamicSharedMemorySize, SM_TOTAL);

    int prep_threads = N_PAD * IN_DIM / 8;   // 802816, covers all prep tasks
    prep_kernel<<<(prep_threads + 255) / 256, 256>>>(x, W1l, W1r, ei);
    scan_kernel<<<1, 1024>>>();
    reorder_kernel<<<(N_EDGES + 255) / 256, 256>>>(ei);
    aggregate1_kernel<<<(N_PAD * 16 + 255) / 256, 256>>>();

    {
        dim3 grid(HID_DIM / 128, N_PAD / 128);
        gemm1_kernel<<<grid, 256, SM_TOTAL>>>(b1, W2l, W2r);
    }

    final_kernel<<<(N_NODES + 255) / 256, 256>>>(b2, out);
}

// round 8
// speedup vs baseline: 1.0809x; 1.0809x over previous
#include <cuda_runtime.h>
#include <cuda_fp16.h>
#include <math.h>
#include <stdint.h>

#define N_NODES 50000
#define N_PAD   50176          // 392 * 128
#define N_EDGES 600000
#define IN_DIM  128
#define HID_DIM 512

// ---------------- scratch ----------------------------------------------------
__device__ int   g_cnt[N_NODES];          // zero-init at load; final_kernel re-zeroes
__device__ int   g_row[N_NODES + 1];
__device__ int   g_cursor[N_NODES];
__device__ int   g_csr[N_EDGES];
__device__ float g_invd[N_NODES];
__device__ __align__(16) __half g_xh  [N_PAD * IN_DIM];
__device__ __align__(16) __half g_aggh[N_PAD * IN_DIM];
__device__ __align__(16) __half g_Wh  [256 * HID_DIM];    // [k][n]: k<128 W1l else W1r
__device__ float g_pq[N_NODES * 4];

__device__ __forceinline__ uint32_t packh2(float a, float b) {
    __half2 h = __floats2half2_rn(a, b);
    return *reinterpret_cast<uint32_t*>(&h);
}

// ---------------- 0. prep: zero pq + convert x/W + histogram -------------------
__global__ void prep_kernel(const float* __restrict__ x,
                            const float* __restrict__ W1l,
                            const float* __restrict__ W1r,
                            const int* __restrict__ edge_index) {
    int i = blockIdx.x * blockDim.x + threadIdx.x;
    if (i < N_NODES * 4) g_pq[i] = 0.f;
    if (i < N_EDGES) atomicAdd(&g_cnt[edge_index[N_EDGES + i]], 1);
    const int xtot = N_PAD * IN_DIM / 8;
    if (i < xtot) {
        long long base = (long long)i * 8;
        int m = (int)(base / IN_DIM);
        uint4 o;
        if (m < N_NODES) {
            float4 v0 = *reinterpret_cast<const float4*>(x + base);
            float4 v1 = *reinterpret_cast<const float4*>(x + base + 4);
            o.x = packh2(v0.x, v0.y); o.y = packh2(v0.z, v0.w);
            o.z = packh2(v1.x, v1.y); o.w = packh2(v1.z, v1.w);
        } else o = make_uint4(0, 0, 0, 0);
        *reinterpret_cast<uint4*>(g_xh + base) = o;
    }
    const int wtot = 256 * HID_DIM / 4;
    if (i < wtot) {
        int base = i * 4;
        int k = base >> 9;
        int n = base & 511;
        const float* W = (k < IN_DIM) ? (W1l + k * HID_DIM + n)
                                      : (W1r + (k - IN_DIM) * HID_DIM + n);
        float4 v = *reinterpret_cast<const float4*>(W);
        uint2 o; o.x = packh2(v.x, v.y); o.y = packh2(v.z, v.w);
        *reinterpret_cast<uint2*>(g_Wh + base) = o;
    }
}

// ---------------- 1. scan -------------------------------------------------------
__global__ void scan_kernel() {
    __shared__ int partial[1024];
    const int t = threadIdx.x;
    const int CHUNK = (N_NODES + 1023) / 1024;
    const int beg = t * CHUNK;
    const int end = min(beg + CHUNK, N_NODES);
    int sum = 0;
    for (int i = beg; i < end; i++) sum += g_cnt[i];
    partial[t] = sum;
    __syncthreads();
    for (int off = 1; off < 1024; off <<= 1) {
        int u = (t >= off) ? partial[t - off] : 0;
        __syncthreads();
        partial[t] += u;
        __syncthreads();
    }
    int run = partial[t] - sum;
    for (int i = beg; i < end; i++) {
        int c = g_cnt[i];
        g_row[i] = run;
        g_cursor[i] = run;
        g_invd[i] = 1.f / fmaxf((float)c, 1.f);
        run += c;
    }
    if (t == 0) g_row[N_NODES] = N_EDGES;
}

// ---------------- 2. reorder ----------------------------------------------------
__global__ void reorder_kernel(const int* __restrict__ edge_index) {
    int e = blockIdx.x * blockDim.x + threadIdx.x;
    if (e >= N_EDGES) return;
    int src = edge_index[e];
    int dst = edge_index[N_EDGES + e];
    int pos = atomicAdd(&g_cursor[dst], 1);
    g_csr[pos] = src;
}

// ---------------- 3. gather-mean aggregation (f16 reads, 16 lanes/node) ----------
__global__ void aggregate1_kernel() {
    int id = blockIdx.x * blockDim.x + threadIdx.x;
    int node = id >> 4;
    int l16 = id & 15;
    if (node >= N_PAD) return;
    float s[8] = {};
    if (node < N_NODES) {
        const int beg = g_row[node];
        const int end = g_row[node + 1];
        int e = beg;
        for (; e + 1 < end; e += 2) {
            int s0 = g_csr[e], s1 = g_csr[e + 1];
            uint4 v0 = *reinterpret_cast<const uint4*>(g_xh + (long long)s0 * IN_DIM + l16 * 8);
            uint4 v1 = *reinterpret_cast<const uint4*>(g_xh + (long long)s1 * IN_DIM + l16 * 8);
            const __half2* h0 = reinterpret_cast<const __half2*>(&v0);
            const __half2* h1 = reinterpret_cast<const __half2*>(&v1);
            #pragma unroll
            for (int j = 0; j < 4; j++) {
                float2 f0 = __half22float2(h0[j]);
                float2 f1 = __half22float2(h1[j]);
                s[j * 2 + 0] += f0.x + f1.x;
                s[j * 2 + 1] += f0.y + f1.y;
            }
        }
        if (e < end) {
            int s0 = g_csr[e];
            uint4 v0 = *reinterpret_cast<const uint4*>(g_xh + (long long)s0 * IN_DIM + l16 * 8);
            const __half2* h0 = reinterpret_cast<const __half2*>(&v0);
            #pragma unroll
            for (int j = 0; j < 4; j++) {
                float2 f0 = __half22float2(h0[j]);
                s[j * 2 + 0] += f0.x;
                s[j * 2 + 1] += f0.y;
            }
        }
        const float invd = g_invd[node];
        #pragma unroll
        for (int j = 0; j < 8; j++) s[j] *= invd;
    }
    uint4 o;
    o.x = packh2(s[0], s[1]); o.y = packh2(s[2], s[3]);
    o.z = packh2(s[4], s[5]); o.w = packh2(s[6], s[7]);
    *reinterpret_cast<uint4*>(g_aggh + (long long)node * IN_DIM + l16 * 8) = o;
}

// ---------------- mma helpers ----------------------------------------------------
__device__ __forceinline__ void ldsm_x4(uint32_t* r, uint32_t addr) {
    asm volatile("ldmatrix.sync.aligned.m8n8.x4.shared.b16 {%0,%1,%2,%3}, [%4];"
                 : "=r"(r[0]), "=r"(r[1]), "=r"(r[2]), "=r"(r[3]) : "r"(addr));
}
__device__ __forceinline__ void ldsm_x2t(uint32_t* r, uint32_t addr) {
    asm volatile("ldmatrix.sync.aligned.m8n8.x2.trans.shared.b16 {%0,%1}, [%2];"
                 : "=r"(r[0]), "=r"(r[1]) : "r"(addr));
}
__device__ __forceinline__ void mma_f16(float* d, const uint32_t* a, const uint32_t* b) {
    asm volatile(
        "mma.sync.aligned.m16n8k16.row.col.f32.f16.f16.f32 "
        "{%0,%1,%2,%3}, {%4,%5,%6,%7}, {%8,%9}, {%0,%1,%2,%3};"
        : "+f"(d[0]), "+f"(d[1]), "+f"(d[2]), "+f"(d[3])
        : "r"(a[0]), "r"(a[1]), "r"(a[2]), "r"(a[3]), "r"(b[0]), "r"(b[1]));
}
__device__ __forceinline__ void cp16(uint32_t smem_addr, const void* gptr) {
    asm volatile("cp.async.cg.shared.global [%0], [%1], 16;"
                 :: "r"(smem_addr), "l"(gptr) : "memory");
}

// ---------------- 4. layer-1 GEMM (fp16 HMMA + cp.async, double-buffered) --------
// BM=128, BN=128, BK=32; 256 threads; warp grid 2x4, warp tile 64x32
__global__ __launch_bounds__(256, 2)
void gemm1_kernel(const float* __restrict__ b1,
                  const float* __restrict__ W2l,
                  const float* __restrict__ W2r) {
    constexpr int BM = 128, BN = 128, BK = 32;
    constexpr int SA = BK + 8;    // 40 halfs = 80B row stride
    constexpr int SB = BN + 8;    // 136 halfs = 272B row stride
    __shared__ __align__(16) __half As[2][BM][SA];
    __shared__ __align__(16) __half Bs[2][BK][SB];
    __shared__ float Wc[BN][4];
    __shared__ float bias_s[BN];

    const int block_m = blockIdx.y * BM;
    const int block_n = blockIdx.x * BN;
    const int tid  = threadIdx.x;
    const int warp = tid >> 5;
    const int lane = tid & 31;
    const int wm = warp >> 2;
    const int wn = warp & 3;
    const int g  = lane >> 2;
    const int t  = lane & 3;

    // epilogue weights/bias
    for (int idx = tid; idx < BN * 4; idx += 256) {
        int nn = idx >> 2, c = idx & 3;
        int n = block_n + nn;
        Wc[nn][c] = (c < 2) ? W2l[n * 2 + c] : W2r[n * 2 + (c - 2)];
    }
    for (int idx = tid; idx < BN; idx += 256) bias_s[idx] = b1[block_n + idx];

    const uint32_t as_base = (uint32_t)__cvta_generic_to_shared(&As[0][0][0]);
    const uint32_t bs_base = (uint32_t)__cvta_generic_to_shared(&Bs[0][0][0]);
    constexpr uint32_t AS_BUF = BM * SA * 2;
    constexpr uint32_t BS_BUF = BK * SB * 2;

    auto load_tile = [&](int k0, int buf) {
        const __half* asrc = (k0 < IN_DIM) ? g_aggh : g_xh;
        const int krel = (k0 < IN_DIM) ? k0 : (k0 - IN_DIM);
        #pragma unroll
        for (int i = 0; i < 2; i++) {
            int id = tid + i * 256;             // 0..511
            int row = id >> 2;                  // 0..127
            int ch = (id & 3) * 8;              // 0,8,16,24
            cp16(as_base + buf * AS_BUF + (row * SA + ch) * 2,
                 asrc + (long long)(block_m + row) * IN_DIM + krel + ch);
        }
        #pragma unroll
        for (int i = 0; i < 2; i++) {
            int id = tid + i * 256;
            int krow = id >> 4;                 // 0..31
            int ncol = (id & 15) * 8;           // 0..120
            cp16(bs_base + buf * BS_BUF + (krow * SB + ncol) * 2,
                 g_Wh + (k0 + krow) * HID_DIM + block_n + ncol);
        }
        asm volatile("cp.async.commit_group;" ::: "memory");
    };

    const uint32_t a_lane = ((wm * 64 + (lane & 15)) * SA + (lane >> 4) * 8) * 2;
    const uint32_t b_lane = ((lane & 15) * SB + wn * 32) * 2;

    float acc[4][4][4] = {};

    constexpr int NT = (2 * IN_DIM) / BK;   // 8 tiles
    load_tile(0, 0);

    #pragma unroll
    for (int tI = 0; tI < NT; tI++) {
        const int buf = tI & 1;
        if (tI + 1 < NT) {
            load_tile((tI + 1) * BK, buf ^ 1);
            asm volatile("cp.async.wait_group 1;" ::: "memory");
        } else {
            asm volatile("cp.async.wait_group 0;" ::: "memory");
        }
        __syncthreads();

        #pragma unroll
        for (int ks = 0; ks < 2; ks++) {
            const int kk = ks * 16;
            uint32_t af[4][4], bf[4][2];
            #pragma unroll
            for (int mi = 0; mi < 4; mi++)
                ldsm_x4(af[mi], as_base + buf * AS_BUF + a_lane + (mi * 16 * SA + kk) * 2);
            #pragma unroll
            for (int ni = 0; ni < 4; ni++)
                ldsm_x2t(bf[ni], bs_base + buf * BS_BUF + b_lane + (kk * SB + ni * 8) * 2);
            #pragma unroll
            for (int mi = 0; mi < 4; mi++)
                #pragma unroll
                for (int ni = 0; ni < 4; ni++)
                    mma_f16(acc[mi][ni], af[mi], bf[ni]);
        }
        __syncthreads();
    }

    // epilogue: bias + relu in-register, project to 4 outputs, reduce over t-quad
    #pragma unroll
    for (int mi = 0; mi < 4; mi++) {
        #pragma unroll
        for (int half = 0; half < 2; half++) {
            const int m = block_m + wm * 64 + mi * 16 + g + half * 8;
            float s0 = 0.f, s1 = 0.f, s2 = 0.f, s3 = 0.f;
            #pragma unroll
            for (int ni = 0; ni < 4; ni++) {
                #pragma unroll
                for (int r = 0; r < 2; r++) {
                    const int nl = wn * 32 + ni * 8 + 2 * t + r;
                    float hv = fmaxf(acc[mi][ni][half * 2 + r] + bias_s[nl], 0.f);
                    s0 += hv * Wc[nl][0];
                    s1 += hv * Wc[nl][1];
                    s2 += hv * Wc[nl][2];
                    s3 += hv * Wc[nl][3];
                }
            }
            #pragma unroll
            for (int off = 1; off <= 2; off <<= 1) {
                s0 += __shfl_xor_sync(0xffffffff, s0, off);
                s1 += __shfl_xor_sync(0xffffffff, s1, off);
                s2 += __shfl_xor_sync(0xffffffff, s2, off);
                s3 += __shfl_xor_sync(0xffffffff, s3, off);
            }
            if (t == 0 && m < N_NODES) {
                atomicAdd(&g_pq[m * 4 + 0], s0);
                atomicAdd(&g_pq[m * 4 + 1], s1);
                atomicAdd(&g_pq[m * 4 + 2], s2);
                atomicAdd(&g_pq[m * 4 + 3], s3);
            }
        }
    }
}

// ---------------- 5. final: gather + log_softmax + reset g_cnt -------------------
__global__ void final_kernel(const float* __restrict__ b2,
                             float* __restrict__ out) {
    int n = blockIdx.x * blockDim.x + threadIdx.x;
    if (n >= N_NODES) return;
    g_cnt[n] = 0;   // restore invariant for next invocation / graph replay
    const int beg = g_row[n];
    const int end = g_row[n + 1];
    float s0 = 0.f, s1 = 0.f;
    int e = beg;
    for (; e + 1 < end; e += 2) {
        int u = g_csr[e], v = g_csr[e + 1];
        float2 pu = *reinterpret_cast<const float2*>(&g_pq[u * 4]);
        float2 pv = *reinterpret_cast<const float2*>(&g_pq[v * 4]);
        s0 += pu.x + pv.x; s1 += pu.y + pv.y;
    }
    if (e < end) {
        int u = g_csr[e];
        float2 pu = *reinterpret_cast<const float2*>(&g_pq[u * 4]);
        s0 += pu.x; s1 += pu.y;
    }
    const float invd = g_invd[n];
    float o0 = s0 * invd + b2[0] + g_pq[n * 4 + 2];
    float o1 = s1 * invd + b2[1] + g_pq[n * 4 + 3];
    float m = fmaxf(o0, o1);
    float lse = m + logf(expf(o0 - m) + expf(o1 - m));
    out[n * 2 + 0] = o0 - lse;
    out[n * 2 + 1] = o1 - lse;
}

// ---------------- launcher ---------------------------------------------------------
extern "C" void kernel_launch(void* const* d_in, const int* in_sizes, int n_in,
                              void* d_out, int out_size) {
    const float* x    = (const float*)d_in[0];
    const float* W1l  = (const float*)d_in[1];
    const float* b1   = (const float*)d_in[2];
    const float* W1r  = (const float*)d_in[3];
    const float* W2l  = (const float*)d_in[4];
    const float* b2   = (const float*)d_in[5];
    const float* W2r  = (const float*)d_in[6];
    const int*   ei   = (const int*)d_in[7];
    float* out = (float*)d_out;

    int prep_threads = N_PAD * IN_DIM / 8;   // 802816, covers all prep tasks
    prep_kernel<<<(prep_threads + 255) / 256, 256>>>(x, W1l, W1r, ei);
    scan_kernel<<<1, 1024>>>();
    reorder_kernel<<<(N_EDGES + 255) / 256, 256>>>(ei);
    aggregate1_kernel<<<(N_PAD * 16 + 255) / 256, 256>>>();

    {
        dim3 grid(HID_DIM / 128, N_PAD / 128);
        gemm1_kernel<<<grid, 256>>>(b1, W2l, W2r);
    }

    final_kernel<<<(N_NODES + 255) / 256, 256>>>(b2, out);
}

// round 9
// speedup vs baseline: 1.1073x; 1.0244x over previous
#include <cuda_runtime.h>
#include <cuda_fp16.h>
#include <math.h>
#include <stdint.h>

#define N_NODES 50000
#define N_PAD   50176          // 392 * 128
#define N_EDGES 600000
#define IN_DIM  128
#define HID_DIM 512

// ---------------- scratch ----------------------------------------------------
__device__ int   g_cnt[N_NODES];          // zero-init at load; final_kernel re-zeroes
__device__ int   g_row[N_NODES + 1];
__device__ int   g_cursor[N_NODES];
__device__ int   g_csr[N_EDGES];
__device__ float g_invd[N_NODES];
__device__ __align__(16) __half g_xh  [N_PAD * IN_DIM];
__device__ __align__(16) __half g_aggh[N_PAD * IN_DIM];
__device__ __align__(16) __half g_Wh  [256 * HID_DIM];    // [k][n]: k<128 W1l else W1r
__device__ float g_pq[N_NODES * 4];

__device__ __forceinline__ uint32_t packh2(float a, float b) {
    __half2 h = __floats2half2_rn(a, b);
    return *reinterpret_cast<uint32_t*>(&h);
}

// ---------------- 0. prep: zero pq + convert x/W + histogram -------------------
__global__ void prep_kernel(const float* __restrict__ x,
                            const float* __restrict__ W1l,
                            const float* __restrict__ W1r,
                            const int* __restrict__ edge_index) {
    int i = blockIdx.x * blockDim.x + threadIdx.x;
    if (i < N_NODES * 4) g_pq[i] = 0.f;
    if (i < N_EDGES) atomicAdd(&g_cnt[edge_index[N_EDGES + i]], 1);
    const int xtot = N_PAD * IN_DIM / 8;
    if (i < xtot) {
        long long base = (long long)i * 8;
        int m = (int)(base / IN_DIM);
        uint4 o;
        if (m < N_NODES) {
            float4 v0 = *reinterpret_cast<const float4*>(x + base);
            float4 v1 = *reinterpret_cast<const float4*>(x + base + 4);
            o.x = packh2(v0.x, v0.y); o.y = packh2(v0.z, v0.w);
            o.z = packh2(v1.x, v1.y); o.w = packh2(v1.z, v1.w);
        } else o = make_uint4(0, 0, 0, 0);
        *reinterpret_cast<uint4*>(g_xh + base) = o;
    }
    const int wtot = 256 * HID_DIM / 4;
    if (i < wtot) {
        int base = i * 4;
        int k = base >> 9;
        int n = base & 511;
        const float* W = (k < IN_DIM) ? (W1l + k * HID_DIM + n)
                                      : (W1r + (k - IN_DIM) * HID_DIM + n);
        float4 v = *reinterpret_cast<const float4*>(W);
        uint2 o; o.x = packh2(v.x, v.y); o.y = packh2(v.z, v.w);
        *reinterpret_cast<uint2*>(g_Wh + base) = o;
    }
}

// ---------------- 1. scan -------------------------------------------------------
__global__ void scan_kernel() {
    __shared__ int partial[1024];
    const int t = threadIdx.x;
    const int CHUNK = (N_NODES + 1023) / 1024;
    const int beg = t * CHUNK;
    const int end = min(beg + CHUNK, N_NODES);
    int sum = 0;
    for (int i = beg; i < end; i++) sum += g_cnt[i];
    partial[t] = sum;
    __syncthreads();
    for (int off = 1; off < 1024; off <<= 1) {
        int u = (t >= off) ? partial[t - off] : 0;
        __syncthreads();
        partial[t] += u;
        __syncthreads();
    }
    int run = partial[t] - sum;
    for (int i = beg; i < end; i++) {
        int c = g_cnt[i];
        g_row[i] = run;
        g_cursor[i] = run;
        g_invd[i] = 1.f / fmaxf((float)c, 1.f);
        run += c;
    }
    if (t == 0) g_row[N_NODES] = N_EDGES;
}

// ---------------- 2. reorder (2 edges/thread, batched loads) ---------------------
__global__ void reorder_kernel(const int* __restrict__ edge_index) {
    int i = blockIdx.x * blockDim.x + threadIdx.x;
    int e0 = i * 2;
    if (e0 >= N_EDGES) return;
    int e1 = e0 + 1;
    int src0 = edge_index[e0];
    int dst0 = edge_index[N_EDGES + e0];
    int src1 = 0, dst1 = 0;
    bool has1 = (e1 < N_EDGES);
    if (has1) {
        src1 = edge_index[e1];
        dst1 = edge_index[N_EDGES + e1];
    }
    int p0 = atomicAdd(&g_cursor[dst0], 1);
    int p1 = has1 ? atomicAdd(&g_cursor[dst1], 1) : 0;
    g_csr[p0] = src0;
    if (has1) g_csr[p1] = src1;
}

// ---------------- 3. gather-mean aggregation (f16 reads, 16 lanes/node) ----------
__global__ void aggregate1_kernel() {
    int id = blockIdx.x * blockDim.x + threadIdx.x;
    int node = id >> 4;
    int l16 = id & 15;
    if (node >= N_PAD) return;
    float s[8] = {};
    if (node < N_NODES) {
        const int beg = g_row[node];
        const int end = g_row[node + 1];
        int e = beg;
        for (; e + 1 < end; e += 2) {
            int s0 = g_csr[e], s1 = g_csr[e + 1];
            uint4 v0 = *reinterpret_cast<const uint4*>(g_xh + (long long)s0 * IN_DIM + l16 * 8);
            uint4 v1 = *reinterpret_cast<const uint4*>(g_xh + (long long)s1 * IN_DIM + l16 * 8);
            const __half2* h0 = reinterpret_cast<const __half2*>(&v0);
            const __half2* h1 = reinterpret_cast<const __half2*>(&v1);
            #pragma unroll
            for (int j = 0; j < 4; j++) {
                float2 f0 = __half22float2(h0[j]);
                float2 f1 = __half22float2(h1[j]);
                s[j * 2 + 0] += f0.x + f1.x;
                s[j * 2 + 1] += f0.y + f1.y;
            }
        }
        if (e < end) {
            int s0 = g_csr[e];
            uint4 v0 = *reinterpret_cast<const uint4*>(g_xh + (long long)s0 * IN_DIM + l16 * 8);
            const __half2* h0 = reinterpret_cast<const __half2*>(&v0);
            #pragma unroll
            for (int j = 0; j < 4; j++) {
                float2 f0 = __half22float2(h0[j]);
                s[j * 2 + 0] += f0.x;
                s[j * 2 + 1] += f0.y;
            }
        }
        const float invd = g_invd[node];
        #pragma unroll
        for (int j = 0; j < 8; j++) s[j] *= invd;
    }
    uint4 o;
    o.x = packh2(s[0], s[1]); o.y = packh2(s[2], s[3]);
    o.z = packh2(s[4], s[5]); o.w = packh2(s[6], s[7]);
    *reinterpret_cast<uint4*>(g_aggh + (long long)node * IN_DIM + l16 * 8) = o;
}

// ---------------- mma helpers ----------------------------------------------------
__device__ __forceinline__ void ldsm_x4(uint32_t* r, uint32_t addr) {
    asm volatile("ldmatrix.sync.aligned.m8n8.x4.shared.b16 {%0,%1,%2,%3}, [%4];"
                 : "=r"(r[0]), "=r"(r[1]), "=r"(r[2]), "=r"(r[3]) : "r"(addr));
}
__device__ __forceinline__ void ldsm_x4t(uint32_t* r, uint32_t addr) {
    asm volatile("ldmatrix.sync.aligned.m8n8.x4.trans.shared.b16 {%0,%1,%2,%3}, [%4];"
                 : "=r"(r[0]), "=r"(r[1]), "=r"(r[2]), "=r"(r[3]) : "r"(addr));
}
__device__ __forceinline__ void mma_f16(float* d, const uint32_t* a, const uint32_t* b) {
    asm volatile(
        "mma.sync.aligned.m16n8k16.row.col.f32.f16.f16.f32 "
        "{%0,%1,%2,%3}, {%4,%5,%6,%7}, {%8,%9}, {%0,%1,%2,%3};"
        : "+f"(d[0]), "+f"(d[1]), "+f"(d[2]), "+f"(d[3])
        : "r"(a[0]), "r"(a[1]), "r"(a[2]), "r"(a[3]), "r"(b[0]), "r"(b[1]));
}
__device__ __forceinline__ void cp16(uint32_t smem_addr, const void* gptr) {
    asm volatile("cp.async.cg.shared.global [%0], [%1], 16;"
                 :: "r"(smem_addr), "l"(gptr) : "memory");
}

// ---------------- 4. layer-1 GEMM: 4-stage cp.async pipeline, 1 sync/tile --------
// BM=128, BN=128, BK=32; 256 threads; warp grid 2x4, warp tile 64x32
#define GK_SA 40                        // A row stride (halfs)
#define GK_SB 136                       // B row stride (halfs)
#define GK_AS 0
#define GK_AS_BUF (128 * GK_SA * 2)     // 10240 bytes per stage
#define GK_BS (4 * GK_AS_BUF)           // 40960
#define GK_BS_BUF (32 * GK_SB * 2)      // 8704 bytes per stage
#define GK_WC (GK_BS + 4 * GK_BS_BUF)   // 75776
#define GK_BIAS (GK_WC + 128 * 4 * 4)   // 77824
#define GK_TOTAL (GK_BIAS + 128 * 4)    // 78336

__global__ __launch_bounds__(256, 2)
void gemm1_kernel(const float* __restrict__ b1,
                  const float* __restrict__ W2l,
                  const float* __restrict__ W2r) {
    extern __shared__ __align__(16) char smem[];
    float (*Wc)[4] = reinterpret_cast<float(*)[4]>(smem + GK_WC);
    float* bias_s = reinterpret_cast<float*>(smem + GK_BIAS);

    const int block_m = blockIdx.y * 128;
    const int block_n = blockIdx.x * 128;
    const int tid  = threadIdx.x;
    const int warp = tid >> 5;
    const int lane = tid & 31;
    const int wm = warp >> 2;
    const int wn = warp & 3;
    const int g  = lane >> 2;
    const int t  = lane & 3;

    const uint32_t sm_base = (uint32_t)__cvta_generic_to_shared(smem);
    const uint32_t as_u = sm_base + GK_AS;
    const uint32_t bs_u = sm_base + GK_BS;

    auto load_tile = [&](int k0, int slot) {
        const __half* asrc = (k0 < IN_DIM) ? g_aggh : g_xh;
        const int krel = (k0 < IN_DIM) ? k0 : (k0 - IN_DIM);
        #pragma unroll
        for (int i = 0; i < 2; i++) {
            int id = tid + i * 256;             // 0..511
            int row = id >> 2;                  // 0..127
            int ch = (id & 3) * 8;              // 0,8,16,24
            cp16(as_u + slot * GK_AS_BUF + (row * GK_SA + ch) * 2,
                 asrc + (long long)(block_m + row) * IN_DIM + krel + ch);
        }
        #pragma unroll
        for (int i = 0; i < 2; i++) {
            int id = tid + i * 256;
            int krow = id >> 4;                 // 0..31
            int ncol = (id & 15) * 8;           // 0..120
            cp16(bs_u + slot * GK_BS_BUF + (krow * GK_SB + ncol) * 2,
                 g_Wh + (k0 + krow) * HID_DIM + block_n + ncol);
        }
        asm volatile("cp.async.commit_group;" ::: "memory");
    };

    // prologue: 3 tiles in flight
    load_tile(0, 0);
    load_tile(32, 1);
    load_tile(64, 2);

    // epilogue weights/bias (plain stores; first pipeline barrier orders them)
    for (int idx = tid; idx < 128 * 4; idx += 256) {
        int nn = idx >> 2, c = idx & 3;
        int n = block_n + nn;
        Wc[nn][c] = (c < 2) ? W2l[n * 2 + c] : W2r[n * 2 + (c - 2)];
    }
    for (int idx = tid; idx < 128; idx += 256) bias_s[idx] = b1[block_n + idx];

    const uint32_t a_lane = ((wm * 64 + (lane & 15)) * GK_SA + (lane >> 4) * 8) * 2;
    const uint32_t b_lane = ((lane & 15) * GK_SB + (lane >> 4) * 8) * 2;

    float acc[4][4][4] = {};
    constexpr int NT = 8;

    #pragma unroll
    for (int tI = 0; tI < NT; tI++) {
        const int buf = tI & 3;
        const int w = (NT - 1 - tI) < 2 ? (NT - 1 - tI) : 2;
        if (w == 2)      asm volatile("cp.async.wait_group 2;" ::: "memory");
        else if (w == 1) asm volatile("cp.async.wait_group 1;" ::: "memory");
        else             asm volatile("cp.async.wait_group 0;" ::: "memory");
        __syncthreads();   // single barrier: data ready + slot (tI-1)%4 reusable

        #pragma unroll
        for (int ks = 0; ks < 2; ks++) {
            const int kk = ks * 16;
            uint32_t af[4][4], bf[4][2];
            #pragma unroll
            for (int mi = 0; mi < 4; mi++)
                ldsm_x4(af[mi], as_u + buf * GK_AS_BUF + a_lane + (mi * 16 * GK_SA + kk) * 2);
            #pragma unroll
            for (int ni2 = 0; ni2 < 2; ni2++) {
                uint32_t r[4];
                ldsm_x4t(r, bs_u + buf * GK_BS_BUF + b_lane + (kk * GK_SB + wn * 32 + ni2 * 16) * 2);
                bf[ni2 * 2 + 0][0] = r[0]; bf[ni2 * 2 + 0][1] = r[1];
                bf[ni2 * 2 + 1][0] = r[2]; bf[ni2 * 2 + 1][1] = r[3];
            }
            #pragma unroll
            for (int mi = 0; mi < 4; mi++)
                #pragma unroll
                for (int ni = 0; ni < 4; ni++)
                    mma_f16(acc[mi][ni], af[mi], bf[ni]);
        }

        if (tI + 3 < NT) load_tile((tI + 3) * 32, (tI + 3) & 3);
    }

    // epilogue: bias + relu in-register, project to 4 outputs, reduce over t-quad
    #pragma unroll
    for (int mi = 0; mi < 4; mi++) {
        #pragma unroll
        for (int half = 0; half < 2; half++) {
            const int m = block_m + wm * 64 + mi * 16 + g + half * 8;
            float s0 = 0.f, s1 = 0.f, s2 = 0.f, s3 = 0.f;
            #pragma unroll
            for (int ni = 0; ni < 4; ni++) {
                #pragma unroll
                for (int r = 0; r < 2; r++) {
                    const int nl = wn * 32 + ni * 8 + 2 * t + r;
                    float hv = fmaxf(acc[mi][ni][half * 2 + r] + bias_s[nl], 0.f);
                    s0 += hv * Wc[nl][0];
                    s1 += hv * Wc[nl][1];
                    s2 += hv * Wc[nl][2];
                    s3 += hv * Wc[nl][3];
                }
            }
            #pragma unroll
            for (int off = 1; off <= 2; off <<= 1) {
                s0 += __shfl_xor_sync(0xffffffff, s0, off);
                s1 += __shfl_xor_sync(0xffffffff, s1, off);
                s2 += __shfl_xor_sync(0xffffffff, s2, off);
                s3 += __shfl_xor_sync(0xffffffff, s3, off);
            }
            if (t == 0 && m < N_NODES) {
                atomicAdd(&g_pq[m * 4 + 0], s0);
                atomicAdd(&g_pq[m * 4 + 1], s1);
                atomicAdd(&g_pq[m * 4 + 2], s2);
                atomicAdd(&g_pq[m * 4 + 3], s3);
            }
        }
    }
}

// ---------------- 5. final: gather + log_softmax + reset g_cnt -------------------
__global__ void final_kernel(const float* __restrict__ b2,
                             float* __restrict__ out) {
    int n = blockIdx.x * blockDim.x + threadIdx.x;
    if (n >= N_NODES) return;
    g_cnt[n] = 0;   // restore invariant for next invocation / graph replay
    const int beg = g_row[n];
    const int end = g_row[n + 1];
    float s0 = 0.f, s1 = 0.f;
    int e = beg;
    for (; e + 1 < end; e += 2) {
        int u = g_csr[e], v = g_csr[e + 1];
        float2 pu = *reinterpret_cast<const float2*>(&g_pq[u * 4]);
        float2 pv = *reinterpret_cast<const float2*>(&g_pq[v * 4]);
        s0 += pu.x + pv.x; s1 += pu.y + pv.y;
    }
    if (e < end) {
        int u = g_csr[e];
        float2 pu = *reinterpret_cast<const float2*>(&g_pq[u * 4]);
        s0 += pu.x; s1 += pu.y;
    }
    const float invd = g_invd[n];
    float o0 = s0 * invd + b2[0] + g_pq[n * 4 + 2];
    float o1 = s1 * invd + b2[1] + g_pq[n * 4 + 3];
    float m = fmaxf(o0, o1);
    float lse = m + logf(expf(o0 - m) + expf(o1 - m));
    out[n * 2 + 0] = o0 - lse;
    out[n * 2 + 1] = o1 - lse;
}

// ---------------- launcher ---------------------------------------------------------
extern "C" void kernel_launch(void* const* d_in, const int* in_sizes, int n_in,
                              void* d_out, int out_size) {
    const float* x    = (const float*)d_in[0];
    const float* W1l  = (const float*)d_in[1];
    const float* b1   = (const float*)d_in[2];
    const float* W1r  = (const float*)d_in[3];
    const float* W2l  = (const float*)d_in[4];
    const float* b2   = (const float*)d_in[5];
    const float* W2r  = (const float*)d_in[6];
    const int*   ei   = (const int*)d_in[7];
    float* out = (float*)d_out;

    cudaFuncSetAttribute(gemm1_kernel,
                         cudaFuncAttributeMaxDynamicSharedMemorySize, GK_TOTAL);

    int prep_threads = N_PAD * IN_DIM / 8;   // 802816, covers all prep tasks
    prep_kernel<<<(prep_threads + 255) / 256, 256>>>(x, W1l, W1r, ei);
    scan_kernel<<<1, 1024>>>();
    reorder_kernel<<<(N_EDGES / 2 + 255) / 256, 256>>>(ei);
    aggregate1_kernel<<<(N_PAD * 16 + 255) / 256, 256>>>();

    {
        dim3 grid(HID_DIM / 128, N_PAD / 128);
        gemm1_kernel<<<grid, 256, GK_TOTAL>>>(b1, W2l, W2r);
    }

    final_kernel<<<(N_NODES + 255) / 256, 256>>>(b2, out);
}

// round 10
// speedup vs baseline: 1.1106x; 1.0030x over previous
#include <cuda_runtime.h>
#include <cuda_fp16.h>
#include <math.h>
#include <stdint.h>

#define N_NODES 50000
#define N_PAD   50176          // 392 * 128
#define N_EDGES 600000
#define IN_DIM  128
#define HID_DIM 512
#define N_MTILES 392
#define GRID_Y 74

// ---------------- scratch ----------------------------------------------------
__device__ int   g_cnt[N_NODES];          // zero-init at load; final_kernel re-zeroes
__device__ int   g_row[N_NODES + 1];
__device__ int   g_cursor[N_NODES];
__device__ int   g_csr[N_EDGES];
__device__ float g_invd[N_NODES];
__device__ __align__(16) __half g_xh  [N_PAD * IN_DIM];
__device__ __align__(16) __half g_aggh[N_PAD * IN_DIM];
__device__ __align__(16) __half g_Wh  [256 * HID_DIM];    // [k][n]: k<128 W1l else W1r
__device__ float g_pq[N_NODES * 4];

__device__ __forceinline__ uint32_t packh2(float a, float b) {
    __half2 h = __floats2half2_rn(a, b);
    return *reinterpret_cast<uint32_t*>(&h);
}

// ---------------- 0. prep: zero pq + convert x/W + histogram -------------------
__global__ void prep_kernel(const float* __restrict__ x,
                            const float* __restrict__ W1l,
                            const float* __restrict__ W1r,
                            const int* __restrict__ edge_index) {
    int i = blockIdx.x * blockDim.x + threadIdx.x;
    if (i < N_NODES * 4) g_pq[i] = 0.f;
    if (i < N_EDGES) atomicAdd(&g_cnt[edge_index[N_EDGES + i]], 1);
    const int xtot = N_PAD * IN_DIM / 8;
    if (i < xtot) {
        long long base = (long long)i * 8;
        int m = (int)(base / IN_DIM);
        uint4 o;
        if (m < N_NODES) {
            float4 v0 = *reinterpret_cast<const float4*>(x + base);
            float4 v1 = *reinterpret_cast<const float4*>(x + base + 4);
            o.x = packh2(v0.x, v0.y); o.y = packh2(v0.z, v0.w);
            o.z = packh2(v1.x, v1.y); o.w = packh2(v1.z, v1.w);
        } else o = make_uint4(0, 0, 0, 0);
        *reinterpret_cast<uint4*>(g_xh + base) = o;
    }
    const int wtot = 256 * HID_DIM / 4;
    if (i < wtot) {
        int base = i * 4;
        int k = base >> 9;
        int n = base & 511;
        const float* W = (k < IN_DIM) ? (W1l + k * HID_DIM + n)
                                      : (W1r + (k - IN_DIM) * HID_DIM + n);
        float4 v = *reinterpret_cast<const float4*>(W);
        uint2 o; o.x = packh2(v.x, v.y); o.y = packh2(v.z, v.w);
        *reinterpret_cast<uint2*>(g_Wh + base) = o;
    }
}

// ---------------- 1. scan -------------------------------------------------------
__global__ void scan_kernel() {
    __shared__ int partial[1024];
    const int t = threadIdx.x;
    const int CHUNK = (N_NODES + 1023) / 1024;
    const int beg = t * CHUNK;
    const int end = min(beg + CHUNK, N_NODES);
    int sum = 0;
    for (int i = beg; i < end; i++) sum += g_cnt[i];
    partial[t] = sum;
    __syncthreads();
    for (int off = 1; off < 1024; off <<= 1) {
        int u = (t >= off) ? partial[t - off] : 0;
        __syncthreads();
        partial[t] += u;
        __syncthreads();
    }
    int run = partial[t] - sum;
    for (int i = beg; i < end; i++) {
        int c = g_cnt[i];
        g_row[i] = run;
        g_cursor[i] = run;
        g_invd[i] = 1.f / fmaxf((float)c, 1.f);
        run += c;
    }
    if (t == 0) g_row[N_NODES] = N_EDGES;
}

// ---------------- 2. reorder (2 edges/thread, batched loads) ---------------------
__global__ void reorder_kernel(const int* __restrict__ edge_index) {
    int i = blockIdx.x * blockDim.x + threadIdx.x;
    int e0 = i * 2;
    if (e0 >= N_EDGES) return;
    int e1 = e0 + 1;
    int src0 = edge_index[e0];
    int dst0 = edge_index[N_EDGES + e0];
    int src1 = 0, dst1 = 0;
    bool has1 = (e1 < N_EDGES);
    if (has1) {
        src1 = edge_index[e1];
        dst1 = edge_index[N_EDGES + e1];
    }
    int p0 = atomicAdd(&g_cursor[dst0], 1);
    int p1 = has1 ? atomicAdd(&g_cursor[dst1], 1) : 0;
    g_csr[p0] = src0;
    if (has1) g_csr[p1] = src1;
}

// ---------------- 3. gather-mean aggregation (f16, 16 lanes/node, 4-way MLP) -----
__global__ void aggregate1_kernel() {
    int id = blockIdx.x * blockDim.x + threadIdx.x;
    int node = id >> 4;
    int l16 = id & 15;
    if (node >= N_PAD) return;
    float s[8] = {};
    if (node < N_NODES) {
        const int beg = g_row[node];
        const int end = g_row[node + 1];
        int e = beg;
        for (; e + 3 < end; e += 4) {
            int i0 = g_csr[e], i1 = g_csr[e + 1], i2 = g_csr[e + 2], i3 = g_csr[e + 3];
            uint4 v0 = *reinterpret_cast<const uint4*>(g_xh + (long long)i0 * IN_DIM + l16 * 8);
            uint4 v1 = *reinterpret_cast<const uint4*>(g_xh + (long long)i1 * IN_DIM + l16 * 8);
            uint4 v2 = *reinterpret_cast<const uint4*>(g_xh + (long long)i2 * IN_DIM + l16 * 8);
            uint4 v3 = *reinterpret_cast<const uint4*>(g_xh + (long long)i3 * IN_DIM + l16 * 8);
            const __half2* h0 = reinterpret_cast<const __half2*>(&v0);
            const __half2* h1 = reinterpret_cast<const __half2*>(&v1);
            const __half2* h2 = reinterpret_cast<const __half2*>(&v2);
            const __half2* h3 = reinterpret_cast<const __half2*>(&v3);
            #pragma unroll
            for (int j = 0; j < 4; j++) {
                float2 f0 = __half22float2(h0[j]);
                float2 f1 = __half22float2(h1[j]);
                float2 f2 = __half22float2(h2[j]);
                float2 f3 = __half22float2(h3[j]);
                s[j * 2 + 0] += (f0.x + f1.x) + (f2.x + f3.x);
                s[j * 2 + 1] += (f0.y + f1.y) + (f2.y + f3.y);
            }
        }
        for (; e < end; e++) {
            int i0 = g_csr[e];
            uint4 v0 = *reinterpret_cast<const uint4*>(g_xh + (long long)i0 * IN_DIM + l16 * 8);
            const __half2* h0 = reinterpret_cast<const __half2*>(&v0);
            #pragma unroll
            for (int j = 0; j < 4; j++) {
                float2 f0 = __half22float2(h0[j]);
                s[j * 2 + 0] += f0.x;
                s[j * 2 + 1] += f0.y;
            }
        }
        const float invd = g_invd[node];
        #pragma unroll
        for (int j = 0; j < 8; j++) s[j] *= invd;
    }
    uint4 o;
    o.x = packh2(s[0], s[1]); o.y = packh2(s[2], s[3]);
    o.z = packh2(s[4], s[5]); o.w = packh2(s[6], s[7]);
    *reinterpret_cast<uint4*>(g_aggh + (long long)node * IN_DIM + l16 * 8) = o;
}

// ---------------- mma helpers ----------------------------------------------------
__device__ __forceinline__ void ldsm_x4(uint32_t* r, uint32_t addr) {
    asm volatile("ldmatrix.sync.aligned.m8n8.x4.shared.b16 {%0,%1,%2,%3}, [%4];"
                 : "=r"(r[0]), "=r"(r[1]), "=r"(r[2]), "=r"(r[3]) : "r"(addr));
}
__device__ __forceinline__ void ldsm_x4t(uint32_t* r, uint32_t addr) {
    asm volatile("ldmatrix.sync.aligned.m8n8.x4.trans.shared.b16 {%0,%1,%2,%3}, [%4];"
                 : "=r"(r[0]), "=r"(r[1]), "=r"(r[2]), "=r"(r[3]) : "r"(addr));
}
__device__ __forceinline__ void mma_f16(float* d, const uint32_t* a, const uint32_t* b) {
    asm volatile(
        "mma.sync.aligned.m16n8k16.row.col.f32.f16.f16.f32 "
        "{%0,%1,%2,%3}, {%4,%5,%6,%7}, {%8,%9}, {%0,%1,%2,%3};"
        : "+f"(d[0]), "+f"(d[1]), "+f"(d[2]), "+f"(d[3])
        : "r"(a[0]), "r"(a[1]), "r"(a[2]), "r"(a[3]), "r"(b[0]), "r"(b[1]));
}
__device__ __forceinline__ void cp16(uint32_t smem_addr, const void* gptr) {
    asm volatile("cp.async.cg.shared.global [%0], [%1], 16;"
                 :: "r"(smem_addr), "l"(gptr) : "memory");
}

// ---------------- 4. persistent GEMM: B resident, A streamed (3-slot pipeline) ---
// Grid 4 x 74 = 296 CTAs (one wave at occ 2). Each CTA: one n-block (128 cols),
// loops m-tiles y, y+74, ... (5-6 tiles). Flat chunk pipeline: 1 barrier/chunk.
#define GP_SA 40
#define GP_SB 136
#define GP_BS 0
#define GP_AS (256 * GP_SB * 2)          // 69632
#define GP_A_BUF (128 * GP_SA * 2)       // 10240 per slot
#define GP_WC (GP_AS + 3 * GP_A_BUF)     // 69632 + 30720 = 100352
#define GP_BIAS (GP_WC + 128 * 4 * 4)    // 102400
#define GP_TOTAL (GP_BIAS + 128 * 4)     // 102912

__global__ __launch_bounds__(256, 2)
void gemm1_kernel(const float* __restrict__ b1,
                  const float* __restrict__ W2l,
                  const float* __restrict__ W2r) {
    extern __shared__ __align__(16) char smem[];
    float (*Wc)[4] = reinterpret_cast<float(*)[4]>(smem + GP_WC);
    float* bias_s = reinterpret_cast<float*>(smem + GP_BIAS);

    const int block_n = blockIdx.x * 128;
    const int y = blockIdx.y;
    const int tid  = threadIdx.x;
    const int warp = tid >> 5;
    const int lane = tid & 31;
    const int wm = warp >> 2;
    const int wn = warp & 3;
    const int g8 = lane >> 2;
    const int t  = lane & 3;

    const uint32_t sm_base = (uint32_t)__cvta_generic_to_shared(smem);
    const uint32_t bs_u = sm_base + GP_BS;
    const uint32_t as_u = sm_base + GP_AS;

    // ---- B slab once: 256 k-rows x 128 n-cols ----
    #pragma unroll
    for (int i = 0; i < 16; i++) {
        int id = tid + i * 256;           // 0..4095
        int k = id >> 4;                  // 0..255
        int nc = (id & 15) * 8;           // 0..120
        cp16(bs_u + (k * GP_SB + nc) * 2, g_Wh + k * HID_DIM + block_n + nc);
    }
    asm volatile("cp.async.commit_group;" ::: "memory");

    const int n_mt = (N_MTILES - y - 1) / GRID_Y + 1;    // 5 or 6
    const int total = n_mt * 8;

    auto load_A = [&](int gidx) {
        const int mt = y + (gidx >> 3) * GRID_Y;
        const int k0 = (gidx & 7) * 32;
        const int slot = gidx % 3;
        const int block_m = mt * 128;
        const __half* asrc = (k0 < IN_DIM) ? g_aggh : g_xh;
        const int krel = (k0 < IN_DIM) ? k0 : (k0 - IN_DIM);
        #pragma unroll
        for (int i = 0; i < 2; i++) {
            int id = tid + i * 256;       // 0..511
            int row = id >> 2;            // 0..127
            int ch = (id & 3) * 8;        // 0,8,16,24
            cp16(as_u + slot * GP_A_BUF + (row * GP_SA + ch) * 2,
                 asrc + (long long)(block_m + row) * IN_DIM + krel + ch);
        }
        asm volatile("cp.async.commit_group;" ::: "memory");
    };

    load_A(0);
    load_A(1);

    // epilogue weights/bias once (plain stores; first barrier orders them)
    for (int idx = tid; idx < 128 * 4; idx += 256) {
        int nn = idx >> 2, c = idx & 3;
        int n = block_n + nn;
        Wc[nn][c] = (c < 2) ? W2l[n * 2 + c] : W2r[n * 2 + (c - 2)];
    }
    for (int idx = tid; idx < 128; idx += 256) bias_s[idx] = b1[block_n + idx];

    const uint32_t a_lane = ((wm * 64 + (lane & 15)) * GP_SA + (lane >> 4) * 8) * 2;
    const uint32_t b_lane = ((lane & 15) * GP_SB + (lane >> 4) * 8) * 2;

    float acc[4][4][4] = {};

    for (int gidx = 0; gidx < total; gidx++) {
        if (gidx + 1 < total) asm volatile("cp.async.wait_group 1;" ::: "memory");
        else                  asm volatile("cp.async.wait_group 0;" ::: "memory");
        __syncthreads();

        const int slot = gidx % 3;
        const int k0 = (gidx & 7) * 32;
        #pragma unroll
        for (int ks = 0; ks < 2; ks++) {
            const int kk = ks * 16;
            uint32_t af[4][4], bf[4][2];
            #pragma unroll
            for (int mi = 0; mi < 4; mi++)
                ldsm_x4(af[mi], as_u + slot * GP_A_BUF + a_lane + (mi * 16 * GP_SA + kk) * 2);
            #pragma unroll
            for (int ni2 = 0; ni2 < 2; ni2++) {
                uint32_t r[4];
                ldsm_x4t(r, bs_u + b_lane + ((k0 + kk) * GP_SB + wn * 32 + ni2 * 16) * 2);
                bf[ni2 * 2 + 0][0] = r[0]; bf[ni2 * 2 + 0][1] = r[1];
                bf[ni2 * 2 + 1][0] = r[2]; bf[ni2 * 2 + 1][1] = r[3];
            }
            #pragma unroll
            for (int mi = 0; mi < 4; mi++)
                #pragma unroll
                for (int ni = 0; ni < 4; ni++)
                    mma_f16(acc[mi][ni], af[mi], bf[ni]);
        }

        if (gidx + 2 < total) load_A(gidx + 2);

        if ((gidx & 7) == 7) {
            // ---- epilogue for this m-tile ----
            const int block_m = (y + (gidx >> 3) * GRID_Y) * 128;
            #pragma unroll
            for (int mi = 0; mi < 4; mi++) {
                #pragma unroll
                for (int half = 0; half < 2; half++) {
                    const int m = block_m + wm * 64 + mi * 16 + g8 + half * 8;
                    float s0 = 0.f, s1 = 0.f, s2 = 0.f, s3 = 0.f;
                    #pragma unroll
                    for (int ni = 0; ni < 4; ni++) {
                        #pragma unroll
                        for (int r = 0; r < 2; r++) {
                            const int nl = wn * 32 + ni * 8 + 2 * t + r;
                            float hv = fmaxf(acc[mi][ni][half * 2 + r] + bias_s[nl], 0.f);
                            s0 += hv * Wc[nl][0];
                            s1 += hv * Wc[nl][1];
                            s2 += hv * Wc[nl][2];
                            s3 += hv * Wc[nl][3];
                        }
                    }
                    #pragma unroll
                    for (int off = 1; off <= 2; off <<= 1) {
                        s0 += __shfl_xor_sync(0xffffffff, s0, off);
                        s1 += __shfl_xor_sync(0xffffffff, s1, off);
                        s2 += __shfl_xor_sync(0xffffffff, s2, off);
                        s3 += __shfl_xor_sync(0xffffffff, s3, off);
                    }
                    if (t == 0 && m < N_NODES) {
                        atomicAdd(&g_pq[m * 4 + 0], s0);
                        atomicAdd(&g_pq[m * 4 + 1], s1);
                        atomicAdd(&g_pq[m * 4 + 2], s2);
                        atomicAdd(&g_pq[m * 4 + 3], s3);
                    }
                }
            }
            #pragma unroll
            for (int mi = 0; mi < 4; mi++)
                #pragma unroll
                for (int ni = 0; ni < 4; ni++)
                    #pragma unroll
                    for (int r = 0; r < 4; r++)
                        acc[mi][ni][r] = 0.f;
        }
    }
}

// ---------------- 5. final: gather + log_softmax + reset g_cnt -------------------
__global__ void final_kernel(const float* __restrict__ b2,
                             float* __restrict__ out) {
    int n = blockIdx.x * blockDim.x + threadIdx.x;
    if (n >= N_NODES) return;
    g_cnt[n] = 0;   // restore invariant for next invocation / graph replay
    const int beg = g_row[n];
    const int end = g_row[n + 1];
    float s0 = 0.f, s1 = 0.f;
    int e = beg;
    for (; e + 1 < end; e += 2) {
        int u = g_csr[e], v = g_csr[e + 1];
        float2 pu = *reinterpret_cast<const float2*>(&g_pq[u * 4]);
        float2 pv = *reinterpret_cast<const float2*>(&g_pq[v * 4]);
        s0 += pu.x + pv.x; s1 += pu.y + pv.y;
    }
    if (e < end) {
        int u = g_csr[e];
        float2 pu = *reinterpret_cast<const float2*>(&g_pq[u * 4]);
        s0 += pu.x; s1 += pu.y;
    }
    const float invd = g_invd[n];
    float o0 = s0 * invd + b2[0] + g_pq[n * 4 + 2];
    float o1 = s1 * invd + b2[1] + g_pq[n * 4 + 3];
    float m = fmaxf(o0, o1);
    float lse = m + logf(expf(o0 - m) + expf(o1 - m));
    out[n * 2 + 0] = o0 - lse;
    out[n * 2 + 1] = o1 - lse;
}

// ---------------- launcher ---------------------------------------------------------
extern "C" void kernel_launch(void* const* d_in, const int* in_sizes, int n_in,
                              void* d_out, int out_size) {
    const float* x    = (const float*)d_in[0];
    const float* W1l  = (const float*)d_in[1];
    const float* b1   = (const float*)d_in[2];
    const float* W1r  = (const float*)d_in[3];
    const float* W2l  = (const float*)d_in[4];
    const float* b2   = (const float*)d_in[5];
    const float* W2r  = (const float*)d_in[6];
    const int*   ei   = (const int*)d_in[7];
    float* out = (float*)d_out;

    cudaFuncSetAttribute(gemm1_kernel,
                         cudaFuncAttributeMaxDynamicSharedMemorySize, GP_TOTAL);

    int prep_threads = N_PAD * IN_DIM / 8;   // 802816, covers all prep tasks
    prep_kernel<<<(prep_threads + 255) / 256, 256>>>(x, W1l, W1r, ei);
    scan_kernel<<<1, 1024>>>();
    reorder_kernel<<<(N_EDGES / 2 + 255) / 256, 256>>>(ei);
    aggregate1_kernel<<<(N_PAD * 16 + 255) / 256, 256>>>();

    {
        dim3 grid(HID_DIM / 128, GRID_Y);
        gemm1_kernel<<<grid, 256, GP_TOTAL>>>(b1, W2l, W2r);
    }

    final_kernel<<<(N_NODES + 255) / 256, 256>>>(b2, out);
}

// round 11
// speedup vs baseline: 1.2425x; 1.1187x over previous
#include <cuda_runtime.h>
#include <cuda_fp16.h>
#include <math.h>
#include <stdint.h>

#define N_NODES 50000
#define N_PAD   50176          // 392 * 128
#define N_EDGES 600000
#define IN_DIM  128
#define HID_DIM 512
#define N_MTILES 392
#define GX_CTAS 784            // 196 m-tiles * 4 n-blocks per half

// ---------------- scratch ----------------------------------------------------
__device__ int   g_cnt[N_NODES];          // zero-init; final_kernel re-zeroes
__device__ int   g_bsum[64];
__device__ int   g_row[N_NODES + 1];
__device__ int   g_cursor[N_NODES];
__device__ int   g_csr[N_EDGES];
__device__ float g_invd[N_NODES];
__device__ __align__(16) __half g_xh  [N_PAD * IN_DIM];
__device__ __align__(16) __half g_aggh[N_PAD * IN_DIM];
__device__ __align__(16) __half g_Wh  [256 * HID_DIM];    // [k][n]: k<128 W1l else W1r
__device__ __align__(16) float  g_hpart[(long long)N_PAD * HID_DIM];  // x @ W1r (f32)
__device__ float g_pq[N_NODES * 4];

__device__ __forceinline__ uint32_t packh2(float a, float b) {
    __half2 h = __floats2half2_rn(a, b);
    return *reinterpret_cast<uint32_t*>(&h);
}

// ---------------- 0. prep: zero pq + convert x/W + histogram -------------------
__global__ void prep_kernel(const float* __restrict__ x,
                            const float* __restrict__ W1l,
                            const float* __restrict__ W1r,
                            const int* __restrict__ edge_index) {
    int i = blockIdx.x * blockDim.x + threadIdx.x;
    if (i < N_NODES * 4) g_pq[i] = 0.f;
    if (i < N_EDGES) atomicAdd(&g_cnt[edge_index[N_EDGES + i]], 1);
    const int xtot = N_PAD * IN_DIM / 8;
    if (i < xtot) {
        long long base = (long long)i * 8;
        int m = (int)(base / IN_DIM);
        uint4 o;
        if (m < N_NODES) {
            float4 v0 = *reinterpret_cast<const float4*>(x + base);
            float4 v1 = *reinterpret_cast<const float4*>(x + base + 4);
            o.x = packh2(v0.x, v0.y); o.y = packh2(v0.z, v0.w);
            o.z = packh2(v1.x, v1.y); o.w = packh2(v1.z, v1.w);
        } else o = make_uint4(0, 0, 0, 0);
        *reinterpret_cast<uint4*>(g_xh + base) = o;
    }
    const int wtot = 256 * HID_DIM / 4;
    if (i < wtot) {
        int base = i * 4;
        int k = base >> 9;
        int n = base & 511;
        const float* W = (k < IN_DIM) ? (W1l + k * HID_DIM + n)
                                      : (W1r + (k - IN_DIM) * HID_DIM + n);
        float4 v = *reinterpret_cast<const float4*>(W);
        uint2 o; o.x = packh2(v.x, v.y); o.y = packh2(v.z, v.w);
        *reinterpret_cast<uint2*>(g_Wh + base) = o;
    }
}

// ---------------- 1. scan phase 1: per-block scan + block sums -----------------
__global__ void scan1_kernel() {
    __shared__ int sm[1024];
    const int b = blockIdx.x, t = threadIdx.x;
    const int i = b * 1024 + t;
    int c = (i < N_NODES) ? g_cnt[i] : 0;
    sm[t] = c;
    __syncthreads();
    for (int off = 1; off < 1024; off <<= 1) {
        int u = (t >= off) ? sm[t - off] : 0;
        __syncthreads();
        sm[t] += u;
        __syncthreads();
    }
    int incl = sm[t];
    if (i < N_NODES) g_row[i] = incl - c;     // intra-block exclusive prefix
    if (t == 1023) g_bsum[b] = incl;
}

// ---------------- 2. scan phase 2: add block offsets, emit cursor/invd ---------
__global__ void scan2_kernel() {
    __shared__ int bs[64];
    const int b = blockIdx.x, t = threadIdx.x;
    if (t < 49) bs[t] = g_bsum[t];
    __syncthreads();
    int boff = 0;
    for (int j = 0; j < b; j++) boff += bs[j];
    const int i = b * 1024 + t;
    if (i < N_NODES) {
        int row = g_row[i] + boff;
        g_row[i] = row;
        g_cursor[i] = row;
        g_invd[i] = 1.f / fmaxf((float)g_cnt[i], 1.f);
    }
    if (b == 0 && t == 0) g_row[N_NODES] = N_EDGES;
}

// ---------------- mma helpers ----------------------------------------------------
__device__ __forceinline__ void ldsm_x4(uint32_t* r, uint32_t addr) {
    asm volatile("ldmatrix.sync.aligned.m8n8.x4.shared.b16 {%0,%1,%2,%3}, [%4];"
                 : "=r"(r[0]), "=r"(r[1]), "=r"(r[2]), "=r"(r[3]) : "r"(addr));
}
__device__ __forceinline__ void ldsm_x4t(uint32_t* r, uint32_t addr) {
    asm volatile("ldmatrix.sync.aligned.m8n8.x4.trans.shared.b16 {%0,%1,%2,%3}, [%4];"
                 : "=r"(r[0]), "=r"(r[1]), "=r"(r[2]), "=r"(r[3]) : "r"(addr));
}
__device__ __forceinline__ void mma_f16(float* d, const uint32_t* a, const uint32_t* b) {
    asm volatile(
        "mma.sync.aligned.m16n8k16.row.col.f32.f16.f16.f32 "
        "{%0,%1,%2,%3}, {%4,%5,%6,%7}, {%8,%9}, {%0,%1,%2,%3};"
        : "+f"(d[0]), "+f"(d[1]), "+f"(d[2]), "+f"(d[3])
        : "r"(a[0]), "r"(a[1]), "r"(a[2]), "r"(a[3]), "r"(b[0]), "r"(b[1]));
}
__device__ __forceinline__ void cp16(uint32_t smem_addr, const void* gptr) {
    asm volatile("cp.async.cg.shared.global [%0], [%1], 16;"
                 :: "r"(smem_addr), "l"(gptr) : "memory");
}

#define SROW 136                          // row stride in halfs (128+8)
#define GX_A 0
#define GX_B (128 * SROW * 2)             // 34816
#define GX_SMEM (2 * 128 * SROW * 2)      // 69632
#define GA_WC GX_SMEM                     // Wc after A+B in gemm_agg
#define GA_BIAS (GA_WC + 128 * 4 * 4)     // +2048
#define GA_SMEM (GA_BIAS + 128 * 4)       // 72192

// ---------------- gemm_x tile: hpart[mt] = x_tile @ W1r_tile (f32 out) -----------
__device__ __forceinline__ void gemmx_tile(int mt, int nb, char* smem, int tid) {
    const uint32_t sm_base = (uint32_t)__cvta_generic_to_shared(smem);
    const uint32_t as_u = sm_base + GX_A;
    const uint32_t bs_u = sm_base + GX_B;
    const int warp = tid >> 5, lane = tid & 31;
    const int wm = warp >> 2, wn = warp & 3;
    const int g8 = lane >> 2, t = lane & 3;
    const int block_m = mt * 128, block_n = nb * 128;

    #pragma unroll
    for (int i = 0; i < 8; i++) {
        int id = tid + i * 256;          // 0..2047
        int row = id >> 4;
        int ch = (id & 15) * 8;
        cp16(as_u + (row * SROW + ch) * 2,
             g_xh + (long long)(block_m + row) * IN_DIM + ch);
    }
    #pragma unroll
    for (int i = 0; i < 8; i++) {
        int id = tid + i * 256;
        int k = id >> 4;
        int nc = (id & 15) * 8;
        cp16(bs_u + (k * SROW + nc) * 2, g_Wh + (128 + k) * HID_DIM + block_n + nc);
    }
    asm volatile("cp.async.commit_group;" ::: "memory");
    asm volatile("cp.async.wait_group 0;" ::: "memory");
    __syncthreads();

    const uint32_t a_lane = ((wm * 64 + (lane & 15)) * SROW + (lane >> 4) * 8) * 2;
    const uint32_t b_lane = ((lane & 15) * SROW + (lane >> 4) * 8) * 2;

    float acc[4][4][4] = {};
    #pragma unroll
    for (int ks = 0; ks < 8; ks++) {
        const int kk = ks * 16;
        uint32_t af[4][4], bf[4][2];
        #pragma unroll
        for (int mi = 0; mi < 4; mi++)
            ldsm_x4(af[mi], as_u + a_lane + (mi * 16 * SROW + kk) * 2);
        #pragma unroll
        for (int ni2 = 0; ni2 < 2; ni2++) {
            uint32_t r[4];
            ldsm_x4t(r, bs_u + b_lane + (kk * SROW + wn * 32 + ni2 * 16) * 2);
            bf[ni2 * 2 + 0][0] = r[0]; bf[ni2 * 2 + 0][1] = r[1];
            bf[ni2 * 2 + 1][0] = r[2]; bf[ni2 * 2 + 1][1] = r[3];
        }
        #pragma unroll
        for (int mi = 0; mi < 4; mi++)
            #pragma unroll
            for (int ni = 0; ni < 4; ni++)
                mma_f16(acc[mi][ni], af[mi], bf[ni]);
    }

    #pragma unroll
    for (int mi = 0; mi < 4; mi++) {
        #pragma unroll
        for (int half = 0; half < 2; half++) {
            const int m = block_m + wm * 64 + mi * 16 + g8 + half * 8;
            #pragma unroll
            for (int ni = 0; ni < 4; ni++) {
                const int n0 = block_n + wn * 32 + ni * 8 + 2 * t;
                float2 v = make_float2(acc[mi][ni][half * 2 + 0],
                                       acc[mi][ni][half * 2 + 1]);
                *reinterpret_cast<float2*>(g_hpart + (long long)m * HID_DIM + n0) = v;
            }
        }
    }
}

// ---------------- 3. K3: gemm_x half 0 (first-scheduled) + reorder ---------------
__global__ __launch_bounds__(256, 2)
void k3_kernel(const int* __restrict__ edge_index) {
    extern __shared__ __align__(16) char smem[];
    if (blockIdx.x < GX_CTAS) {
        gemmx_tile((int)(blockIdx.x >> 2), (int)(blockIdx.x & 3), smem, threadIdx.x);
        return;
    }
    int id = (blockIdx.x - GX_CTAS) * 256 + threadIdx.x;
    int e0 = id * 2;
    if (e0 >= N_EDGES) return;
    int e1 = e0 + 1;
    int src0 = edge_index[e0];
    int dst0 = edge_index[N_EDGES + e0];
    int src1 = 0, dst1 = 0;
    bool has1 = (e1 < N_EDGES);
    if (has1) { src1 = edge_index[e1]; dst1 = edge_index[N_EDGES + e1]; }
    int p0 = atomicAdd(&g_cursor[dst0], 1);
    int p1 = has1 ? atomicAdd(&g_cursor[dst1], 1) : 0;
    g_csr[p0] = src0;
    if (has1) g_csr[p1] = src1;
}

// ---------------- 4. K4: gemm_x half 1 + gather-mean aggregation -----------------
__global__ __launch_bounds__(256, 2)
void k4_kernel() {
    extern __shared__ __align__(16) char smem[];
    if (blockIdx.x < GX_CTAS) {
        gemmx_tile(196 + (int)(blockIdx.x >> 2), (int)(blockIdx.x & 3), smem, threadIdx.x);
        return;
    }
    int id = (blockIdx.x - GX_CTAS) * 256 + threadIdx.x;
    int node = id >> 4;
    int l16 = id & 15;
    if (node >= N_PAD) return;
    float s[8] = {};
    if (node < N_NODES) {
        const int beg = g_row[node];
        const int end = g_row[node + 1];
        int e = beg;
        for (; e + 3 < end; e += 4) {
            int i0 = g_csr[e], i1 = g_csr[e + 1], i2 = g_csr[e + 2], i3 = g_csr[e + 3];
            uint4 v0 = *reinterpret_cast<const uint4*>(g_xh + (long long)i0 * IN_DIM + l16 * 8);
            uint4 v1 = *reinterpret_cast<const uint4*>(g_xh + (long long)i1 * IN_DIM + l16 * 8);
            uint4 v2 = *reinterpret_cast<const uint4*>(g_xh + (long long)i2 * IN_DIM + l16 * 8);
            uint4 v3 = *reinterpret_cast<const uint4*>(g_xh + (long long)i3 * IN_DIM + l16 * 8);
            const __half2* h0 = reinterpret_cast<const __half2*>(&v0);
            const __half2* h1 = reinterpret_cast<const __half2*>(&v1);
            const __half2* h2 = reinterpret_cast<const __half2*>(&v2);
            const __half2* h3 = reinterpret_cast<const __half2*>(&v3);
            #pragma unroll
            for (int j = 0; j < 4; j++) {
                float2 f0 = __half22float2(h0[j]);
                float2 f1 = __half22float2(h1[j]);
                float2 f2 = __half22float2(h2[j]);
                float2 f3 = __half22float2(h3[j]);
                s[j * 2 + 0] += (f0.x + f1.x) + (f2.x + f3.x);
                s[j * 2 + 1] += (f0.y + f1.y) + (f2.y + f3.y);
            }
        }
        for (; e < end; e++) {
            int i0 = g_csr[e];
            uint4 v0 = *reinterpret_cast<const uint4*>(g_xh + (long long)i0 * IN_DIM + l16 * 8);
            const __half2* h0 = reinterpret_cast<const __half2*>(&v0);
            #pragma unroll
            for (int j = 0; j < 4; j++) {
                float2 f0 = __half22float2(h0[j]);
                s[j * 2 + 0] += f0.x;
                s[j * 2 + 1] += f0.y;
            }
        }
        const float invd = g_invd[node];
        #pragma unroll
        for (int j = 0; j < 8; j++) s[j] *= invd;
    }
    uint4 o;
    o.x = packh2(s[0], s[1]); o.y = packh2(s[2], s[3]);
    o.z = packh2(s[4], s[5]); o.w = packh2(s[6], s[7]);
    *reinterpret_cast<uint4*>(g_aggh + (long long)node * IN_DIM + l16 * 8) = o;
}

// ---------------- 5. gemm_agg: agg@W1l + hpart, relu, project, accumulate --------
__global__ __launch_bounds__(256, 2)
void gemm_agg_kernel(const float* __restrict__ b1,
                     const float* __restrict__ W2l,
                     const float* __restrict__ W2r) {
    extern __shared__ __align__(16) char smem[];
    float (*Wc)[4] = reinterpret_cast<float(*)[4]>(smem + GA_WC);
    float* bias_s = reinterpret_cast<float*>(smem + GA_BIAS);

    const uint32_t sm_base = (uint32_t)__cvta_generic_to_shared(smem);
    const uint32_t as_u = sm_base + GX_A;
    const uint32_t bs_u = sm_base + GX_B;
    const int tid = threadIdx.x;
    const int warp = tid >> 5, lane = tid & 31;
    const int wm = warp >> 2, wn = warp & 3;
    const int g8 = lane >> 2, t = lane & 3;
    const int block_m = blockIdx.y * 128;
    const int block_n = blockIdx.x * 128;

    #pragma unroll
    for (int i = 0; i < 8; i++) {
        int id = tid + i * 256;
        int row = id >> 4;
        int ch = (id & 15) * 8;
        cp16(as_u + (row * SROW + ch) * 2,
             g_aggh + (long long)(block_m + row) * IN_DIM + ch);
    }
    #pragma unroll
    for (int i = 0; i < 8; i++) {
        int id = tid + i * 256;
        int k = id >> 4;
        int nc = (id & 15) * 8;
        cp16(bs_u + (k * SROW + nc) * 2, g_Wh + k * HID_DIM + block_n + nc);
    }
    asm volatile("cp.async.commit_group;" ::: "memory");

    for (int idx = tid; idx < 128 * 4; idx += 256) {
        int nn = idx >> 2, c = idx & 3;
        int n = block_n + nn;
        Wc[nn][c] = (c < 2) ? W2l[n * 2 + c] : W2r[n * 2 + (c - 2)];
    }
    for (int idx = tid; idx < 128; idx += 256) bias_s[idx] = b1[block_n + idx];

    asm volatile("cp.async.wait_group 0;" ::: "memory");
    __syncthreads();

    const uint32_t a_lane = ((wm * 64 + (lane & 15)) * SROW + (lane >> 4) * 8) * 2;
    const uint32_t b_lane = ((lane & 15) * SROW + (lane >> 4) * 8) * 2;

    float acc[4][4][4] = {};
    #pragma unroll
    for (int ks = 0; ks < 8; ks++) {
        const int kk = ks * 16;
        uint32_t af[4][4], bf[4][2];
        #pragma unroll
        for (int mi = 0; mi < 4; mi++)
            ldsm_x4(af[mi], as_u + a_lane + (mi * 16 * SROW + kk) * 2);
        #pragma unroll
        for (int ni2 = 0; ni2 < 2; ni2++) {
            uint32_t r[4];
            ldsm_x4t(r, bs_u + b_lane + (kk * SROW + wn * 32 + ni2 * 16) * 2);
            bf[ni2 * 2 + 0][0] = r[0]; bf[ni2 * 2 + 0][1] = r[1];
            bf[ni2 * 2 + 1][0] = r[2]; bf[ni2 * 2 + 1][1] = r[3];
        }
        #pragma unroll
        for (int mi = 0; mi < 4; mi++)
            #pragma unroll
            for (int ni = 0; ni < 4; ni++)
                mma_f16(acc[mi][ni], af[mi], bf[ni]);
    }

    // epilogue: + hpart + bias, relu, project, reduce over t-quad, accumulate
    #pragma unroll
    for (int mi = 0; mi < 4; mi++) {
        #pragma unroll
        for (int half = 0; half < 2; half++) {
            const int m = block_m + wm * 64 + mi * 16 + g8 + half * 8;
            float s0 = 0.f, s1 = 0.f, s2 = 0.f, s3 = 0.f;
            #pragma unroll
            for (int ni = 0; ni < 4; ni++) {
                const int nl = wn * 32 + ni * 8 + 2 * t;
                float2 hp = *reinterpret_cast<const float2*>(
                    g_hpart + (long long)m * HID_DIM + block_n + nl);
                #pragma unroll
                for (int r = 0; r < 2; r++) {
                    float hpv = (r == 0) ? hp.x : hp.y;
                    float hv = fmaxf(acc[mi][ni][half * 2 + r] + hpv + bias_s[nl + r], 0.f);
                    s0 += hv * Wc[nl + r][0];
                    s1 += hv * Wc[nl + r][1];
                    s2 += hv * Wc[nl + r][2];
                    s3 += hv * Wc[nl + r][3];
                }
            }
            #pragma unroll
            for (int off = 1; off <= 2; off <<= 1) {
                s0 += __shfl_xor_sync(0xffffffff, s0, off);
                s1 += __shfl_xor_sync(0xffffffff, s1, off);
                s2 += __shfl_xor_sync(0xffffffff, s2, off);
                s3 += __shfl_xor_sync(0xffffffff, s3, off);
            }
            if (t == 0 && m < N_NODES) {
                atomicAdd(&g_pq[m * 4 + 0], s0);
                atomicAdd(&g_pq[m * 4 + 1], s1);
                atomicAdd(&g_pq[m * 4 + 2], s2);
                atomicAdd(&g_pq[m * 4 + 3], s3);
            }
        }
    }
}

// ---------------- 6. final: gather + log_softmax + reset g_cnt -------------------
__global__ void final_kernel(const float* __restrict__ b2,
                             float* __restrict__ out) {
    int n = blockIdx.x * blockDim.x + threadIdx.x;
    if (n >= N_NODES) return;
    g_cnt[n] = 0;   // restore invariant for next invocation / graph replay
    const int beg = g_row[n];
    const int end = g_row[n + 1];
    float s0 = 0.f, s1 = 0.f;
    int e = beg;
    for (; e + 1 < end; e += 2) {
        int u = g_csr[e], v = g_csr[e + 1];
        float2 pu = *reinterpret_cast<const float2*>(&g_pq[u * 4]);
        float2 pv = *reinterpret_cast<const float2*>(&g_pq[v * 4]);
        s0 += pu.x + pv.x; s1 += pu.y + pv.y;
    }
    if (e < end) {
        int u = g_csr[e];
        float2 pu = *reinterpret_cast<const float2*>(&g_pq[u * 4]);
        s0 += pu.x; s1 += pu.y;
    }
    const float invd = g_invd[n];
    float o0 = s0 * invd + b2[0] + g_pq[n * 4 + 2];
    float o1 = s1 * invd + b2[1] + g_pq[n * 4 + 3];
    float m = fmaxf(o0, o1);
    float lse = m + logf(expf(o0 - m) + expf(o1 - m));
    out[n * 2 + 0] = o0 - lse;
    out[n * 2 + 1] = o1 - lse;
}

// ---------------- launcher ---------------------------------------------------------
extern "C" void kernel_launch(void* const* d_in, const int* in_sizes, int n_in,
                              void* d_out, int out_size) {
    const float* x    = (const float*)d_in[0];
    const float* W1l  = (const float*)d_in[1];
    const float* b1   = (const float*)d_in[2];
    const float* W1r  = (const float*)d_in[3];
    const float* W2l  = (const float*)d_in[4];
    const float* b2   = (const float*)d_in[5];
    const float* W2r  = (const float*)d_in[6];
    const int*   ei   = (const int*)d_in[7];
    float* out = (float*)d_out;

    cudaFuncSetAttribute(k3_kernel,
                         cudaFuncAttributeMaxDynamicSharedMemorySize, GX_SMEM);
    cudaFuncSetAttribute(k4_kernel,
                         cudaFuncAttributeMaxDynamicSharedMemorySize, GX_SMEM);
    cudaFuncSetAttribute(gemm_agg_kernel,
                         cudaFuncAttributeMaxDynamicSharedMemorySize, GA_SMEM);

    int prep_threads = N_PAD * IN_DIM / 8;   // 802816, covers all prep tasks
    prep_kernel<<<(prep_threads + 255) / 256, 256>>>(x, W1l, W1r, ei);
    scan1_kernel<<<49, 1024>>>();
    scan2_kernel<<<49, 1024>>>();

    {   // gemm_x half 0 + reorder
        int reorder_blocks = (N_EDGES / 2 + 255) / 256;          // 1172
        k3_kernel<<<GX_CTAS + reorder_blocks, 256, GX_SMEM>>>(ei);
    }
    {   // gemm_x half 1 + aggregate
        int agg_blocks = (N_PAD * 16) / 256;                      // 3136
        k4_kernel<<<GX_CTAS + agg_blocks, 256, GX_SMEM>>>();
    }
    {
        dim3 grid(HID_DIM / 128, N_MTILES);
        gemm_agg_kernel<<<grid, 256, GA_SMEM>>>(b1, W2l, W2r);
    }
    final_kernel<<<(N_NODES + 255) / 256, 256>>>(b2, out);
}

// round 12
// speedup vs baseline: 1.3920x; 1.1204x over previous
#include <cuda_runtime.h>
#include <cuda_fp16.h>
#include <math.h>
#include <stdint.h>

#define N_NODES 50000
#define N_PAD   50176          // 392 * 128
#define N_EDGES 600000
#define IN_DIM  128
#define HID_DIM 512
#define N_MTILES 392
#define GX_CTAS 784            // 196 m-tiles * 4 n-blocks per half

// ---------------- scratch ----------------------------------------------------
__device__ int   g_cnt[N_NODES];          // zero-init; final_kernel re-zeroes
__device__ int   g_bsum[64];
__device__ int   g_row[N_NODES + 1];
__device__ int   g_cursor[N_NODES];
__device__ int   g_csr[N_EDGES];
__device__ float g_invd[N_NODES];
__device__ __align__(16) __half g_xh  [N_PAD * IN_DIM];
__device__ __align__(16) __half g_aggh[N_PAD * IN_DIM];
__device__ __align__(16) __half g_Wh  [256 * HID_DIM];    // [k][n]: k<128 W1l else W1r
__device__ __align__(16) __half g_hparth[(long long)N_PAD * HID_DIM];  // x @ W1r (f16)
__device__ float g_pq[N_NODES * 4];

__device__ __forceinline__ uint32_t packh2(float a, float b) {
    __half2 h = __floats2half2_rn(a, b);
    return *reinterpret_cast<uint32_t*>(&h);
}

// ---------------- 0. prep: zero pq + convert x/W + histogram -------------------
__global__ void prep_kernel(const float* __restrict__ x,
                            const float* __restrict__ W1l,
                            const float* __restrict__ W1r,
                            const int* __restrict__ edge_index) {
    int i = blockIdx.x * blockDim.x + threadIdx.x;
    if (i < N_NODES * 4) g_pq[i] = 0.f;
    if (i < N_EDGES) atomicAdd(&g_cnt[edge_index[N_EDGES + i]], 1);
    const int xtot = N_PAD * IN_DIM / 8;
    if (i < xtot) {
        long long base = (long long)i * 8;
        int m = (int)(base / IN_DIM);
        uint4 o;
        if (m < N_NODES) {
            float4 v0 = *reinterpret_cast<const float4*>(x + base);
            float4 v1 = *reinterpret_cast<const float4*>(x + base + 4);
            o.x = packh2(v0.x, v0.y); o.y = packh2(v0.z, v0.w);
            o.z = packh2(v1.x, v1.y); o.w = packh2(v1.z, v1.w);
        } else o = make_uint4(0, 0, 0, 0);
        *reinterpret_cast<uint4*>(g_xh + base) = o;
    }
    const int wtot = 256 * HID_DIM / 4;
    if (i < wtot) {
        int base = i * 4;
        int k = base >> 9;
        int n = base & 511;
        const float* W = (k < IN_DIM) ? (W1l + k * HID_DIM + n)
                                      : (W1r + (k - IN_DIM) * HID_DIM + n);
        float4 v = *reinterpret_cast<const float4*>(W);
        uint2 o; o.x = packh2(v.x, v.y); o.y = packh2(v.z, v.w);
        *reinterpret_cast<uint2*>(g_Wh + base) = o;
    }
}

// ---------------- 1. scan phase 1 ------------------------------------------------
__global__ void scan1_kernel() {
    __shared__ int sm[1024];
    const int b = blockIdx.x, t = threadIdx.x;
    const int i = b * 1024 + t;
    int c = (i < N_NODES) ? g_cnt[i] : 0;
    sm[t] = c;
    __syncthreads();
    for (int off = 1; off < 1024; off <<= 1) {
        int u = (t >= off) ? sm[t - off] : 0;
        __syncthreads();
        sm[t] += u;
        __syncthreads();
    }
    int incl = sm[t];
    if (i < N_NODES) g_row[i] = incl - c;
    if (t == 1023) g_bsum[b] = incl;
}

// ---------------- 2. scan phase 2 ------------------------------------------------
__global__ void scan2_kernel() {
    __shared__ int bs[64];
    const int b = blockIdx.x, t = threadIdx.x;
    if (t < 49) bs[t] = g_bsum[t];
    __syncthreads();
    int boff = 0;
    for (int j = 0; j < b; j++) boff += bs[j];
    const int i = b * 1024 + t;
    if (i < N_NODES) {
        int row = g_row[i] + boff;
        g_row[i] = row;
        g_cursor[i] = row;
        g_invd[i] = 1.f / fmaxf((float)g_cnt[i], 1.f);
    }
    if (b == 0 && t == 0) g_row[N_NODES] = N_EDGES;
}

// ---------------- mma helpers ----------------------------------------------------
__device__ __forceinline__ void ldsm_x4(uint32_t* r, uint32_t addr) {
    asm volatile("ldmatrix.sync.aligned.m8n8.x4.shared.b16 {%0,%1,%2,%3}, [%4];"
                 : "=r"(r[0]), "=r"(r[1]), "=r"(r[2]), "=r"(r[3]) : "r"(addr));
}
__device__ __forceinline__ void ldsm_x4t(uint32_t* r, uint32_t addr) {
    asm volatile("ldmatrix.sync.aligned.m8n8.x4.trans.shared.b16 {%0,%1,%2,%3}, [%4];"
                 : "=r"(r[0]), "=r"(r[1]), "=r"(r[2]), "=r"(r[3]) : "r"(addr));
}
__device__ __forceinline__ void mma_f16(float* d, const uint32_t* a, const uint32_t* b) {
    asm volatile(
        "mma.sync.aligned.m16n8k16.row.col.f32.f16.f16.f32 "
        "{%0,%1,%2,%3}, {%4,%5,%6,%7}, {%8,%9}, {%0,%1,%2,%3};"
        : "+f"(d[0]), "+f"(d[1]), "+f"(d[2]), "+f"(d[3])
        : "r"(a[0]), "r"(a[1]), "r"(a[2]), "r"(a[3]), "r"(b[0]), "r"(b[1]));
}
__device__ __forceinline__ void cp16(uint32_t smem_addr, const void* gptr) {
    asm volatile("cp.async.cg.shared.global [%0], [%1], 16;"
                 :: "r"(smem_addr), "l"(gptr) : "memory");
}

#define SROW 136                          // row stride in halfs (128+8)
#define GX_A 0
#define GX_B (128 * SROW * 2)             // 34816
#define GX_SMEM (2 * 128 * SROW * 2)      // 69632
#define GA_WC GX_SMEM
#define GA_BIAS (GA_WC + 128 * 4 * 4)
#define GA_SMEM (GA_BIAS + 128 * 4)       // 72192

// ---------------- gemm_x tile: hpart[mt] = x_tile @ W1r_tile (f16 out) -----------
// 2-phase k-chunk pipeline: chunk0 (k 0..63), chunk1 (k 64..127)
__device__ __forceinline__ void gemmx_tile(int mt, int nb, char* smem, int tid) {
    const uint32_t sm_base = (uint32_t)__cvta_generic_to_shared(smem);
    const uint32_t as_u = sm_base + GX_A;
    const uint32_t bs_u = sm_base + GX_B;
    const int warp = tid >> 5, lane = tid & 31;
    const int wm = warp >> 2, wn = warp & 3;
    const int g8 = lane >> 2, t = lane & 3;
    const int block_m = mt * 128, block_n = nb * 128;

    #pragma unroll
    for (int ph = 0; ph < 2; ph++) {
        const int kb = ph * 64;
        #pragma unroll
        for (int i = 0; i < 4; i++) {
            int id = tid + i * 256;      // 0..1023
            int row = id >> 3;           // 0..127
            int ch = (id & 7) * 8;       // 0..56
            cp16(as_u + (row * SROW + kb + ch) * 2,
                 g_xh + (long long)(block_m + row) * IN_DIM + kb + ch);
        }
        #pragma unroll
        for (int i = 0; i < 4; i++) {
            int id = tid + i * 256;      // 0..1023
            int k = id >> 4;             // 0..63
            int nc = (id & 15) * 8;      // 0..120
            cp16(bs_u + ((kb + k) * SROW + nc) * 2,
                 g_Wh + (128 + kb + k) * HID_DIM + block_n + nc);
        }
        asm volatile("cp.async.commit_group;" ::: "memory");
    }

    const uint32_t a_lane = ((wm * 64 + (lane & 15)) * SROW + (lane >> 4) * 8) * 2;
    const uint32_t b_lane = ((lane & 15) * SROW + (lane >> 4) * 8) * 2;

    float acc[4][4][4] = {};
    #pragma unroll
    for (int ph = 0; ph < 2; ph++) {
        if (ph == 0) asm volatile("cp.async.wait_group 1;" ::: "memory");
        else         asm volatile("cp.async.wait_group 0;" ::: "memory");
        __syncthreads();
        #pragma unroll
        for (int ks = 0; ks < 4; ks++) {
            const int kk = ph * 64 + ks * 16;
            uint32_t af[4][4], bf[4][2];
            #pragma unroll
            for (int mi = 0; mi < 4; mi++)
                ldsm_x4(af[mi], as_u + a_lane + (mi * 16 * SROW + kk) * 2);
            #pragma unroll
            for (int ni2 = 0; ni2 < 2; ni2++) {
                uint32_t r[4];
                ldsm_x4t(r, bs_u + b_lane + (kk * SROW + wn * 32 + ni2 * 16) * 2);
                bf[ni2 * 2 + 0][0] = r[0]; bf[ni2 * 2 + 0][1] = r[1];
                bf[ni2 * 2 + 1][0] = r[2]; bf[ni2 * 2 + 1][1] = r[3];
            }
            #pragma unroll
            for (int mi = 0; mi < 4; mi++)
                #pragma unroll
                for (int ni = 0; ni < 4; ni++)
                    mma_f16(acc[mi][ni], af[mi], bf[ni]);
        }
    }

    #pragma unroll
    for (int mi = 0; mi < 4; mi++) {
        #pragma unroll
        for (int half = 0; half < 2; half++) {
            const int m = block_m + wm * 64 + mi * 16 + g8 + half * 8;
            #pragma unroll
            for (int ni = 0; ni < 4; ni++) {
                const int n0 = block_n + wn * 32 + ni * 8 + 2 * t;
                uint32_t v = packh2(acc[mi][ni][half * 2 + 0],
                                    acc[mi][ni][half * 2 + 1]);
                *reinterpret_cast<uint32_t*>(g_hparth + (long long)m * HID_DIM + n0) = v;
            }
        }
    }
}

// ---------------- 3. K3: gemm_x half 0 + reorder ---------------------------------
__global__ __launch_bounds__(256, 2)
void k3_kernel(const int* __restrict__ edge_index) {
    extern __shared__ __align__(16) char smem[];
    if (blockIdx.x < GX_CTAS) {
        gemmx_tile((int)(blockIdx.x >> 2), (int)(blockIdx.x & 3), smem, threadIdx.x);
        return;
    }
    int id = (blockIdx.x - GX_CTAS) * 256 + threadIdx.x;
    int e0 = id * 2;
    if (e0 >= N_EDGES) return;
    int e1 = e0 + 1;
    int src0 = edge_index[e0];
    int dst0 = edge_index[N_EDGES + e0];
    int src1 = 0, dst1 = 0;
    bool has1 = (e1 < N_EDGES);
    if (has1) { src1 = edge_index[e1]; dst1 = edge_index[N_EDGES + e1]; }
    int p0 = atomicAdd(&g_cursor[dst0], 1);
    int p1 = has1 ? atomicAdd(&g_cursor[dst1], 1) : 0;
    g_csr[p0] = src0;
    if (has1) g_csr[p1] = src1;
}

// ---------------- 4. K4: gemm_x half 1 + gather-mean aggregation -----------------
__global__ __launch_bounds__(256, 2)
void k4_kernel() {
    extern __shared__ __align__(16) char smem[];
    if (blockIdx.x < GX_CTAS) {
        gemmx_tile(196 + (int)(blockIdx.x >> 2), (int)(blockIdx.x & 3), smem, threadIdx.x);
        return;
    }
    int id = (blockIdx.x - GX_CTAS) * 256 + threadIdx.x;
    int node = id >> 4;
    int l16 = id & 15;
    if (node >= N_PAD) return;
    float s[8] = {};
    if (node < N_NODES) {
        const int beg = g_row[node];
        const int end = g_row[node + 1];
        int e = beg;
        for (; e + 3 < end; e += 4) {
            int i0 = g_csr[e], i1 = g_csr[e + 1], i2 = g_csr[e + 2], i3 = g_csr[e + 3];
            uint4 v0 = *reinterpret_cast<const uint4*>(g_xh + (long long)i0 * IN_DIM + l16 * 8);
            uint4 v1 = *reinterpret_cast<const uint4*>(g_xh + (long long)i1 * IN_DIM + l16 * 8);
            uint4 v2 = *reinterpret_cast<const uint4*>(g_xh + (long long)i2 * IN_DIM + l16 * 8);
            uint4 v3 = *reinterpret_cast<const uint4*>(g_xh + (long long)i3 * IN_DIM + l16 * 8);
            const __half2* h0 = reinterpret_cast<const __half2*>(&v0);
            const __half2* h1 = reinterpret_cast<const __half2*>(&v1);
            const __half2* h2 = reinterpret_cast<const __half2*>(&v2);
            const __half2* h3 = reinterpret_cast<const __half2*>(&v3);
            #pragma unroll
            for (int j = 0; j < 4; j++) {
                float2 f0 = __half22float2(h0[j]);
                float2 f1 = __half22float2(h1[j]);
                float2 f2 = __half22float2(h2[j]);
                float2 f3 = __half22float2(h3[j]);
                s[j * 2 + 0] += (f0.x + f1.x) + (f2.x + f3.x);
                s[j * 2 + 1] += (f0.y + f1.y) + (f2.y + f3.y);
            }
        }
        for (; e < end; e++) {
            int i0 = g_csr[e];
            uint4 v0 = *reinterpret_cast<const uint4*>(g_xh + (long long)i0 * IN_DIM + l16 * 8);
            const __half2* h0 = reinterpret_cast<const __half2*>(&v0);
            #pragma unroll
            for (int j = 0; j < 4; j++) {
                float2 f0 = __half22float2(h0[j]);
                s[j * 2 + 0] += f0.x;
                s[j * 2 + 1] += f0.y;
            }
        }
        const float invd = g_invd[node];
        #pragma unroll
        for (int j = 0; j < 8; j++) s[j] *= invd;
    }
    uint4 o;
    o.x = packh2(s[0], s[1]); o.y = packh2(s[2], s[3]);
    o.z = packh2(s[4], s[5]); o.w = packh2(s[6], s[7]);
    *reinterpret_cast<uint4*>(g_aggh + (long long)node * IN_DIM + l16 * 8) = o;
}

// ---------------- 5. gemm_agg: agg@W1l + hpart, relu, project, accumulate --------
__global__ __launch_bounds__(256, 2)
void gemm_agg_kernel(const float* __restrict__ b1,
                     const float* __restrict__ W2l,
                     const float* __restrict__ W2r) {
    extern __shared__ __align__(16) char smem[];
    float (*Wc)[4] = reinterpret_cast<float(*)[4]>(smem + GA_WC);
    float* bias_s = reinterpret_cast<float*>(smem + GA_BIAS);

    const uint32_t sm_base = (uint32_t)__cvta_generic_to_shared(smem);
    const uint32_t as_u = sm_base + GX_A;
    const uint32_t bs_u = sm_base + GX_B;
    const int tid = threadIdx.x;
    const int warp = tid >> 5, lane = tid & 31;
    const int wm = warp >> 2, wn = warp & 3;
    const int g8 = lane >> 2, t = lane & 3;
    const int block_m = blockIdx.y * 128;
    const int block_n = blockIdx.x * 128;

    #pragma unroll
    for (int ph = 0; ph < 2; ph++) {
        const int kb = ph * 64;
        #pragma unroll
        for (int i = 0; i < 4; i++) {
            int id = tid + i * 256;
            int row = id >> 3;
            int ch = (id & 7) * 8;
            cp16(as_u + (row * SROW + kb + ch) * 2,
                 g_aggh + (long long)(block_m + row) * IN_DIM + kb + ch);
        }
        #pragma unroll
        for (int i = 0; i < 4; i++) {
            int id = tid + i * 256;
            int k = id >> 4;
            int nc = (id & 15) * 8;
            cp16(bs_u + ((kb + k) * SROW + nc) * 2,
                 g_Wh + (kb + k) * HID_DIM + block_n + nc);
        }
        asm volatile("cp.async.commit_group;" ::: "memory");
    }

    for (int idx = tid; idx < 128 * 4; idx += 256) {
        int nn = idx >> 2, c = idx & 3;
        int n = block_n + nn;
        Wc[nn][c] = (c < 2) ? W2l[n * 2 + c] : W2r[n * 2 + (c - 2)];
    }
    for (int idx = tid; idx < 128; idx += 256) bias_s[idx] = b1[block_n + idx];

    const uint32_t a_lane = ((wm * 64 + (lane & 15)) * SROW + (lane >> 4) * 8) * 2;
    const uint32_t b_lane = ((lane & 15) * SROW + (lane >> 4) * 8) * 2;

    float acc[4][4][4] = {};
    #pragma unroll
    for (int ph = 0; ph < 2; ph++) {
        if (ph == 0) asm volatile("cp.async.wait_group 1;" ::: "memory");
        else         asm volatile("cp.async.wait_group 0;" ::: "memory");
        __syncthreads();
        #pragma unroll
        for (int ks = 0; ks < 4; ks++) {
            const int kk = ph * 64 + ks * 16;
            uint32_t af[4][4], bf[4][2];
            #pragma unroll
            for (int mi = 0; mi < 4; mi++)
                ldsm_x4(af[mi], as_u + a_lane + (mi * 16 * SROW + kk) * 2);
            #pragma unroll
            for (int ni2 = 0; ni2 < 2; ni2++) {
                uint32_t r[4];
                ldsm_x4t(r, bs_u + b_lane + (kk * SROW + wn * 32 + ni2 * 16) * 2);
                bf[ni2 * 2 + 0][0] = r[0]; bf[ni2 * 2 + 0][1] = r[1];
                bf[ni2 * 2 + 1][0] = r[2]; bf[ni2 * 2 + 1][1] = r[3];
            }
            #pragma unroll
            for (int mi = 0; mi < 4; mi++)
                #pragma unroll
                for (int ni = 0; ni < 4; ni++)
                    mma_f16(acc[mi][ni], af[mi], bf[ni]);
        }
    }

    // epilogue: + hpart(f16) + bias, relu, project, reduce over t-quad, accumulate
    #pragma unroll
    for (int mi = 0; mi < 4; mi++) {
        #pragma unroll
        for (int half = 0; half < 2; half++) {
            const int m = block_m + wm * 64 + mi * 16 + g8 + half * 8;
            float s0 = 0.f, s1 = 0.f, s2 = 0.f, s3 = 0.f;
            #pragma unroll
            for (int ni = 0; ni < 4; ni++) {
                const int nl = wn * 32 + ni * 8 + 2 * t;
                __half2 hh = *reinterpret_cast<const __half2*>(
                    g_hparth + (long long)m * HID_DIM + block_n + nl);
                float2 hp = __half22float2(hh);
                #pragma unroll
                for (int r = 0; r < 2; r++) {
                    float hpv = (r == 0) ? hp.x : hp.y;
                    float hv = fmaxf(acc[mi][ni][half * 2 + r] + hpv + bias_s[nl + r], 0.f);
                    s0 += hv * Wc[nl + r][0];
                    s1 += hv * Wc[nl + r][1];
                    s2 += hv * Wc[nl + r][2];
                    s3 += hv * Wc[nl + r][3];
                }
            }
            #pragma unroll
            for (int off = 1; off <= 2; off <<= 1) {
                s0 += __shfl_xor_sync(0xffffffff, s0, off);
                s1 += __shfl_xor_sync(0xffffffff, s1, off);
                s2 += __shfl_xor_sync(0xffffffff, s2, off);
                s3 += __shfl_xor_sync(0xffffffff, s3, off);
            }
            if (t == 0 && m < N_NODES) {
                atomicAdd(&g_pq[m * 4 + 0], s0);
                atomicAdd(&g_pq[m * 4 + 1], s1);
                atomicAdd(&g_pq[m * 4 + 2], s2);
                atomicAdd(&g_pq[m * 4 + 3], s3);
            }
        }
    }
}

// ---------------- 6. final: gather + log_softmax + reset g_cnt -------------------
__global__ void final_kernel(const float* __restrict__ b2,
                             float* __restrict__ out) {
    int n = blockIdx.x * blockDim.x + threadIdx.x;
    if (n >= N_NODES) return;
    g_cnt[n] = 0;
    const int beg = g_row[n];
    const int end = g_row[n + 1];
    float s0 = 0.f, s1 = 0.f;
    int e = beg;
    for (; e + 1 < end; e += 2) {
        int u = g_csr[e], v = g_csr[e + 1];
        float2 pu = *reinterpret_cast<const float2*>(&g_pq[u * 4]);
        float2 pv = *reinterpret_cast<const float2*>(&g_pq[v * 4]);
        s0 += pu.x + pv.x; s1 += pu.y + pv.y;
    }
    if (e < end) {
        int u = g_csr[e];
        float2 pu = *reinterpret_cast<const float2*>(&g_pq[u * 4]);
        s0 += pu.x; s1 += pu.y;
    }
    const float invd = g_invd[n];
    float o0 = s0 * invd + b2[0] + g_pq[n * 4 + 2];
    float o1 = s1 * invd + b2[1] + g_pq[n * 4 + 3];
    float m = fmaxf(o0, o1);
    float lse = m + logf(expf(o0 - m) + expf(o1 - m));
    out[n * 2 + 0] = o0 - lse;
    out[n * 2 + 1] = o1 - lse;
}

// ---------------- launcher ---------------------------------------------------------
extern "C" void kernel_launch(void* const* d_in, const int* in_sizes, int n_in,
                              void* d_out, int out_size) {
    const float* x    = (const float*)d_in[0];
    const float* W1l  = (const float*)d_in[1];
    const float* b1   = (const float*)d_in[2];
    const float* W1r  = (const float*)d_in[3];
    const float* W2l  = (const float*)d_in[4];
    const float* b2   = (const float*)d_in[5];
    const float* W2r  = (const float*)d_in[6];
    const int*   ei   = (const int*)d_in[7];
    float* out = (float*)d_out;

    cudaFuncSetAttribute(k3_kernel,
                         cudaFuncAttributeMaxDynamicSharedMemorySize, GX_SMEM);
    cudaFuncSetAttribute(k4_kernel,
                         cudaFuncAttributeMaxDynamicSharedMemorySize, GX_SMEM);
    cudaFuncSetAttribute(gemm_agg_kernel,
                         cudaFuncAttributeMaxDynamicSharedMemorySize, GA_SMEM);

    int prep_threads = N_PAD * IN_DIM / 8;
    prep_kernel<<<(prep_threads + 255) / 256, 256>>>(x, W1l, W1r, ei);
    scan1_kernel<<<49, 1024>>>();
    scan2_kernel<<<49, 1024>>>();

    {   // gemm_x half 0 + reorder
        int reorder_blocks = (N_EDGES / 2 + 255) / 256;          // 1172
        k3_kernel<<<GX_CTAS + reorder_blocks, 256, GX_SMEM>>>(ei);
    }
    {   // gemm_x half 1 + aggregate
        int agg_blocks = (N_PAD * 16) / 256;                      // 3136
        k4_kernel<<<GX_CTAS + agg_blocks, 256, GX_SMEM>>>();
    }
    {
        dim3 grid(HID_DIM / 128, N_MTILES);
        gemm_agg_kernel<<<grid, 256, GA_SMEM>>>(b1, W2l, W2r);
    }
    final_kernel<<<(N_NODES + 255) / 256, 256>>>(b2, out);
}